// round 1
// baseline (speedup 1.0000x reference)
#include <cuda_runtime.h>
#include <math.h>

#define BATCH 2
#define NPTS  16384
#define KNB   32
#define C     128
#define MTOT  (BATCH*NPTS)   // 32768
#define LN_EPS 1e-5f

// scratch (device globals; no runtime allocation)
__device__ float g_s  [(size_t)MTOT*C];   // 16 MB
__device__ float g_res[(size_t)MTOT*C];   // 16 MB
__device__ float g_A  [3*C];
__device__ float g_Bm [3*C];
__device__ float g_wd [C];
__device__ float g_b2 [C];

// ---------------------------------------------------------------------------
// K1: fold w_pos through w_gcm.
// w_pg[i][c] = sum_j w_pos[i][j]*w_gcm[j][c]
// A  = P0-P2 (center coeffs), Bm = P1+P2 (neighbor coeffs), wd = p3 (dist),
// b2 = b_pos@w_gcm + b_gcm
// ---------------------------------------------------------------------------
__global__ void k_prep(const float* __restrict__ w_pos, const float* __restrict__ b_pos,
                       const float* __restrict__ w_gcm, const float* __restrict__ b_gcm)
{
    int c = threadIdx.x;  // 128 threads
    float pg[10];
#pragma unroll
    for (int i = 0; i < 10; i++) {
        float acc = 0.f;
        for (int j = 0; j < C; j++) acc = fmaf(w_pos[i*C + j], w_gcm[j*C + c], acc);
        pg[i] = acc;
    }
    float b2 = b_gcm[c];
    for (int j = 0; j < C; j++) b2 = fmaf(b_pos[j], w_gcm[j*C + c], b2);
#pragma unroll
    for (int d = 0; d < 3; d++) {
        g_A [d*C + c] = pg[d]     - pg[6 + d];
        g_Bm[d*C + c] = pg[3 + d] + pg[6 + d];
    }
    g_wd[c] = pg[9];
    g_b2[c] = b2;
}

// ---------------------------------------------------------------------------
// K2: g_s[m] = features[m] @ w_gcm + points[m]·Bm
// 128x128 CTA tile, 256 threads, 8x8 microtile, KC=32 chunks.
// ---------------------------------------------------------------------------
__global__ __launch_bounds__(256) void k_gemm_s(
    const float* __restrict__ feat, const float* __restrict__ wg,
    const float* __restrict__ pts)
{
    __shared__ float as[128][36];
    __shared__ float ws[32][128];
    const int tid = threadIdx.x;
    const int tx = tid & 15, ty = tid >> 4;
    const int row0 = blockIdx.x * 128;
    const int r0 = ty * 8, c0 = tx * 8;

    float acc[8][8];
#pragma unroll
    for (int i = 0; i < 8; i++)
#pragma unroll
        for (int j = 0; j < 8; j++) acc[i][j] = 0.f;

    for (int kc = 0; kc < 128; kc += 32) {
#pragma unroll
        for (int q = tid; q < 1024; q += 256) {
            int row = q >> 3, kq = (q & 7) << 2;
            float4 v = *(const float4*)&feat[(size_t)(row0 + row)*C + kc + kq];
            *(float4*)&as[row][kq] = v;
        }
#pragma unroll
        for (int q = tid; q < 1024; q += 256) {
            int kr = q >> 5, cq = (q & 31) << 2;
            float4 v = *(const float4*)&wg[(size_t)(kc + kr)*C + cq];
            *(float4*)&ws[kr][cq] = v;
        }
        __syncthreads();
#pragma unroll 8
        for (int k = 0; k < 32; k++) {
            float a[8], w[8];
#pragma unroll
            for (int i = 0; i < 8; i++) a[i] = as[r0 + i][k];
            float4 w0 = *(const float4*)&ws[k][c0];
            float4 w1 = *(const float4*)&ws[k][c0 + 4];
            w[0]=w0.x; w[1]=w0.y; w[2]=w0.z; w[3]=w0.w;
            w[4]=w1.x; w[5]=w1.y; w[6]=w1.z; w[7]=w1.w;
#pragma unroll
            for (int i = 0; i < 8; i++)
#pragma unroll
                for (int j = 0; j < 8; j++)
                    acc[i][j] = fmaf(a[i], w[j], acc[i][j]);
        }
        __syncthreads();
    }

    // epilogue: + points·Bm, store
    float bm[3][8];
#pragma unroll
    for (int d = 0; d < 3; d++)
#pragma unroll
        for (int j = 0; j < 8; j++) bm[d][j] = g_Bm[d*C + c0 + j];

#pragma unroll
    for (int i = 0; i < 8; i++) {
        int r = row0 + r0 + i;
        float px = pts[r*3 + 0], py = pts[r*3 + 1], pz = pts[r*3 + 2];
#pragma unroll
        for (int j = 0; j < 8; j++)
            acc[i][j] = fmaf(px, bm[0][j], fmaf(py, bm[1][j], fmaf(pz, bm[2][j], acc[i][j])));
        float4 o0 = make_float4(acc[i][0], acc[i][1], acc[i][2], acc[i][3]);
        float4 o1 = make_float4(acc[i][4], acc[i][5], acc[i][6], acc[i][7]);
        *(float4*)&g_s[(size_t)r*C + c0]     = o0;
        *(float4*)&g_s[(size_t)r*C + c0 + 4] = o1;
    }
}

// ---------------------------------------------------------------------------
// K3: warp per point. lane = 4 channels (coalesced float4 row gathers).
// pooled = relu(max_k(s[idx_k] + dist_k*wd) + u[n]); res = pooled + features
// ---------------------------------------------------------------------------
__global__ __launch_bounds__(256) void k_pool(
    const float* __restrict__ pts, const float* __restrict__ feat,
    const int* __restrict__ gidx)
{
    const int gtid = blockIdx.x * 256 + threadIdx.x;
    const int pt   = gtid >> 5;            // 0..32767, grid exact
    const int lane = threadIdx.x & 31;
    const int base = (pt >> 14) << 14;     // batch base row

    const float cx = pts[pt*3 + 0], cy = pts[pt*3 + 1], cz = pts[pt*3 + 2];

    int j = gidx[pt*KNB + lane] + base;    // global gathered row for this lane's k
    const float* gp = &pts[(size_t)j*3];
    float dx = gp[0] - cx, dy = gp[1] - cy, dz = gp[2] - cz;
    float dist = sqrtf(fmaf(dx, dx, fmaf(dy, dy, dz*dz)));

    const int c0 = lane << 2;
    const float4 wd = *(const float4*)&g_wd[c0];
    float4 acc = make_float4(-3.0e38f, -3.0e38f, -3.0e38f, -3.0e38f);

#pragma unroll
    for (int k = 0; k < 32; k++) {
        int   jk = __shfl_sync(0xffffffffu, j,    k);
        float dk = __shfl_sync(0xffffffffu, dist, k);
        float4 sv = *(const float4*)&g_s[(size_t)jk*C + c0];
        acc.x = fmaxf(acc.x, fmaf(dk, wd.x, sv.x));
        acc.y = fmaxf(acc.y, fmaf(dk, wd.y, sv.y));
        acc.z = fmaxf(acc.z, fmaf(dk, wd.z, sv.z));
        acc.w = fmaxf(acc.w, fmaf(dk, wd.w, sv.w));
    }

    const float4 a0 = *(const float4*)&g_A[c0];
    const float4 a1 = *(const float4*)&g_A[C + c0];
    const float4 a2 = *(const float4*)&g_A[2*C + c0];
    const float4 b2 = *(const float4*)&g_b2[c0];
    const float4 f  = *(const float4*)&feat[(size_t)pt*C + c0];

    float4 r;
    r.x = fmaxf(acc.x + fmaf(cx, a0.x, fmaf(cy, a1.x, fmaf(cz, a2.x, b2.x))), 0.f) + f.x;
    r.y = fmaxf(acc.y + fmaf(cx, a0.y, fmaf(cy, a1.y, fmaf(cz, a2.y, b2.y))), 0.f) + f.y;
    r.z = fmaxf(acc.z + fmaf(cx, a0.z, fmaf(cy, a1.z, fmaf(cz, a2.z, b2.z))), 0.f) + f.z;
    r.w = fmaxf(acc.w + fmaf(cx, a0.w, fmaf(cy, a1.w, fmaf(cz, a2.w, b2.w))), 0.f) + f.w;

    *(float4*)&g_res[(size_t)pt*C + c0] = r;
}

// ---------------------------------------------------------------------------
// K4: out = relu(LN(res @ w_out + b_out) * ln_g + ln_b)
// 64x128 CTA tile, 256 threads, 4x8 microtile; LN epilogue via smem.
// ---------------------------------------------------------------------------
__global__ __launch_bounds__(256) void k_gemm_ln(
    const float* __restrict__ wout, const float* __restrict__ bout,
    const float* __restrict__ lng,  const float* __restrict__ lnb,
    float* __restrict__ out)
{
    __shared__ float sh[8448];
    float* as_ = sh;             // [64][36]  = 2304
    float* ws_ = sh + 2304;      // [32][128] = 4096
    const int tid = threadIdx.x;
    const int tx = tid & 15, ty = tid >> 4;
    const int row0 = blockIdx.x * 64;
    const int r0 = ty * 4, c0 = tx * 8;

    float acc[4][8];
#pragma unroll
    for (int i = 0; i < 4; i++)
#pragma unroll
        for (int j = 0; j < 8; j++) acc[i][j] = 0.f;

    for (int kc = 0; kc < 128; kc += 32) {
#pragma unroll
        for (int q = tid; q < 512; q += 256) {
            int row = q >> 3, kq = (q & 7) << 2;
            float4 v = *(const float4*)&g_res[(size_t)(row0 + row)*C + kc + kq];
            *(float4*)&as_[row*36 + kq] = v;
        }
#pragma unroll
        for (int q = tid; q < 1024; q += 256) {
            int kr = q >> 5, cq = (q & 31) << 2;
            float4 v = *(const float4*)&wout[(size_t)(kc + kr)*C + cq];
            *(float4*)&ws_[kr*C + cq] = v;
        }
        __syncthreads();
#pragma unroll 8
        for (int k = 0; k < 32; k++) {
            float a[4], w[8];
#pragma unroll
            for (int i = 0; i < 4; i++) a[i] = as_[(r0 + i)*36 + k];
            float4 w0 = *(const float4*)&ws_[k*C + c0];
            float4 w1 = *(const float4*)&ws_[k*C + c0 + 4];
            w[0]=w0.x; w[1]=w0.y; w[2]=w0.z; w[3]=w0.w;
            w[4]=w1.x; w[5]=w1.y; w[6]=w1.z; w[7]=w1.w;
#pragma unroll
            for (int i = 0; i < 4; i++)
#pragma unroll
                for (int j = 0; j < 8; j++)
                    acc[i][j] = fmaf(a[i], w[j], acc[i][j]);
        }
        __syncthreads();
    }

    // epilogue: +bias -> smem tile, row stats, LN + relu, coalesced store
    float* so  = sh;             // [64][129] = 8256
    float* smu = sh + 8256;      // 64
    float* srs = sh + 8320;      // 64

#pragma unroll
    for (int j = 0; j < 8; j++) {
        float bj = bout[c0 + j];
#pragma unroll
        for (int i = 0; i < 4; i++)
            so[(r0 + i)*129 + c0 + j] = acc[i][j] + bj;
    }
    __syncthreads();

    if (tid < 64) {
        float sum = 0.f, ss = 0.f;
#pragma unroll 16
        for (int c = 0; c < 128; c++) {
            float x = so[tid*129 + c];
            sum += x;
            ss = fmaf(x, x, ss);
        }
        float mu  = sum * (1.f/128.f);
        float var = fmaf(ss, 1.f/128.f, -mu*mu);
        smu[tid] = mu;
        srs[tid] = rsqrtf(var + LN_EPS);
    }
    __syncthreads();

#pragma unroll
    for (int e = tid; e < 64*128; e += 256) {
        int r = e >> 7, c = e & 127;
        float x = so[r*129 + c];
        float y = fmaf((x - smu[r]) * srs[r], lng[c], lnb[c]);
        out[(size_t)(row0 + r)*C + c] = fmaxf(y, 0.f);
    }
}

// ---------------------------------------------------------------------------
extern "C" void kernel_launch(void* const* d_in, const int* in_sizes, int n_in,
                              void* d_out, int out_size)
{
    const float* points = (const float*)d_in[0];
    const float* feat   = (const float*)d_in[1];
    const int*   gidx   = (const int*)  d_in[2];
    const float* w_pos  = (const float*)d_in[3];
    const float* b_pos  = (const float*)d_in[4];
    const float* w_gcm  = (const float*)d_in[5];
    const float* b_gcm  = (const float*)d_in[6];
    const float* w_out  = (const float*)d_in[7];
    const float* b_out  = (const float*)d_in[8];
    const float* ln_g   = (const float*)d_in[9];
    const float* ln_b   = (const float*)d_in[10];
    float* out = (float*)d_out;

    k_prep   <<<1,            128>>>(w_pos, b_pos, w_gcm, b_gcm);
    k_gemm_s <<<MTOT/128,     256>>>(feat, w_gcm, points);
    k_pool   <<<MTOT*32/256,  256>>>(points, feat, gidx);
    k_gemm_ln<<<MTOT/64,      256>>>(w_out, b_out, ln_g, ln_b, out);
}

// round 2
// speedup vs baseline: 1.2248x; 1.2248x over previous
#include <cuda_runtime.h>
#include <math.h>

#define BATCH 2
#define NPTS  16384
#define KNB   32
#define C     128
#define MTOT  (BATCH*NPTS)   // 32768
#define LN_EPS 1e-5f

// scratch (device globals; no runtime allocation)
__device__ float g_s  [(size_t)MTOT*C];   // 16 MB
__device__ float g_A  [3*C];
__device__ float g_Bm [3*C];
__device__ float g_wd [C];
__device__ float g_b2 [C];

typedef unsigned long long u64;

__device__ __forceinline__ u64 pack2(float x, float y) {
    u64 r; asm("mov.b64 %0,{%1,%2};" : "=l"(r) : "f"(x), "f"(y)); return r;
}
__device__ __forceinline__ u64 fma2(u64 a, u64 b, u64 c) {
    u64 d; asm("fma.rn.f32x2 %0,%1,%2,%3;" : "=l"(d) : "l"(a), "l"(b), "l"(c)); return d;
}
__device__ __forceinline__ float2 unpack2(u64 v) {
    float2 f; asm("mov.b64 {%0,%1},%2;" : "=f"(f.x), "=f"(f.y) : "l"(v)); return f;
}

// ---------------------------------------------------------------------------
// K1: fold w_pos through w_gcm.
// ---------------------------------------------------------------------------
__global__ void k_prep(const float* __restrict__ w_pos, const float* __restrict__ b_pos,
                       const float* __restrict__ w_gcm, const float* __restrict__ b_gcm)
{
    int c = threadIdx.x;  // 128 threads
    float pg[10];
#pragma unroll
    for (int i = 0; i < 10; i++) {
        float acc = 0.f;
        for (int j = 0; j < C; j++) acc = fmaf(w_pos[i*C + j], w_gcm[j*C + c], acc);
        pg[i] = acc;
    }
    float b2 = b_gcm[c];
    for (int j = 0; j < C; j++) b2 = fmaf(b_pos[j], w_gcm[j*C + c], b2);
#pragma unroll
    for (int d = 0; d < 3; d++) {
        g_A [d*C + c] = pg[d]     - pg[6 + d];
        g_Bm[d*C + c] = pg[3 + d] + pg[6 + d];
    }
    g_wd[c] = pg[9];
    g_b2[c] = b2;
}

// ---------------------------------------------------------------------------
// K2: g_s[m] = features[m] @ w_gcm + points[m]·Bm   (f32x2 packed FMA)
// 128x128 CTA tile, 256 threads, 8x8 microtile, KC=32 chunks.
// ---------------------------------------------------------------------------
__global__ __launch_bounds__(256, 2) void k_gemm_s(
    const float* __restrict__ feat, const float* __restrict__ wg,
    const float* __restrict__ pts)
{
    __shared__ float as[128][36];
    __shared__ float ws[32][128];
    const int tid = threadIdx.x;
    const int tx = tid & 15, ty = tid >> 4;
    const int row0 = blockIdx.x * 128;
    const int r0 = ty * 8, c0 = tx * 8;

    u64 acc2[8][4];
#pragma unroll
    for (int i = 0; i < 8; i++)
#pragma unroll
        for (int j = 0; j < 4; j++) acc2[i][j] = 0ull;

    for (int kc = 0; kc < 128; kc += 32) {
#pragma unroll
        for (int q = tid; q < 1024; q += 256) {
            int row = q >> 3, kq = (q & 7) << 2;
            float4 v = *(const float4*)&feat[(size_t)(row0 + row)*C + kc + kq];
            *(float4*)&as[row][kq] = v;
        }
#pragma unroll
        for (int q = tid; q < 1024; q += 256) {
            int kr = q >> 5, cq = (q & 31) << 2;
            float4 v = *(const float4*)&wg[(size_t)(kc + kr)*C + cq];
            *(float4*)&ws[kr][cq] = v;
        }
        __syncthreads();
#pragma unroll 8
        for (int k = 0; k < 32; k++) {
            ulonglong2 wA = *(const ulonglong2*)&ws[k][c0];
            ulonglong2 wB = *(const ulonglong2*)&ws[k][c0 + 4];
            u64 w2[4] = { wA.x, wA.y, wB.x, wB.y };
#pragma unroll
            for (int i = 0; i < 8; i++) {
                float a = as[r0 + i][k];
                u64 a2 = pack2(a, a);
#pragma unroll
                for (int j = 0; j < 4; j++)
                    acc2[i][j] = fma2(a2, w2[j], acc2[i][j]);
            }
        }
        __syncthreads();
    }

    // epilogue: + points·Bm, store
    float bm[3][8];
#pragma unroll
    for (int d = 0; d < 3; d++)
#pragma unroll
        for (int j = 0; j < 8; j++) bm[d][j] = g_Bm[d*C + c0 + j];

#pragma unroll
    for (int i = 0; i < 8; i++) {
        int r = row0 + r0 + i;
        float px = pts[r*3 + 0], py = pts[r*3 + 1], pz = pts[r*3 + 2];
        float acc[8];
#pragma unroll
        for (int j = 0; j < 4; j++) {
            float2 v = unpack2(acc2[i][j]);
            acc[2*j] = v.x; acc[2*j + 1] = v.y;
        }
#pragma unroll
        for (int j = 0; j < 8; j++)
            acc[j] = fmaf(px, bm[0][j], fmaf(py, bm[1][j], fmaf(pz, bm[2][j], acc[j])));
        float4 o0 = make_float4(acc[0], acc[1], acc[2], acc[3]);
        float4 o1 = make_float4(acc[4], acc[5], acc[6], acc[7]);
        *(float4*)&g_s[(size_t)r*C + c0]     = o0;
        *(float4*)&g_s[(size_t)r*C + c0 + 4] = o1;
    }
}

// ---------------------------------------------------------------------------
// K3 (fused): per-CTA pool 128 rows into smem, then res @ w_out GEMM with
// fused bias + LayerNorm + relu epilogue. Eliminates g_res round-trip.
// Dynamic smem: a[128][132] + ws[32][128] + mu[128] + rs[128] = 84992 B.
// ---------------------------------------------------------------------------
#define APAD 132
#define FUSED_SMEM ((128*APAD + 32*128 + 256) * 4)

__global__ __launch_bounds__(256, 2) void k_fused(
    const float* __restrict__ pts,  const float* __restrict__ feat,
    const int*   __restrict__ gidx,
    const float* __restrict__ wout, const float* __restrict__ bout,
    const float* __restrict__ lng,  const float* __restrict__ lnb,
    float* __restrict__ out)
{
    extern __shared__ float sh[];
    float* a_sm = sh;                    // [128][APAD]
    float* ws_  = sh + 128*APAD;         // [32][128]
    float* smu  = ws_ + 32*128;          // [128]
    float* srs  = smu + 128;             // [128]

    const int tid  = threadIdx.x;
    const int wid  = tid >> 5;
    const int lane = tid & 31;
    const int row0 = blockIdx.x * 128;

    // ---- Phase A: pool 128 points into a_sm (warp w handles 16 points) ----
    {
        const int c0 = lane << 2;
        const float4 wd = *(const float4*)&g_wd[c0];
        const float4 a0 = *(const float4*)&g_A[c0];
        const float4 a1 = *(const float4*)&g_A[C + c0];
        const float4 a2 = *(const float4*)&g_A[2*C + c0];
        const float4 b2 = *(const float4*)&g_b2[c0];

        for (int t = 0; t < 16; t++) {
            const int pl = wid * 16 + t;        // local row
            const int pt = row0 + pl;
            const int base = (pt >> 14) << 14;  // batch base row

            const float cx = pts[pt*3 + 0], cy = pts[pt*3 + 1], cz = pts[pt*3 + 2];
            int j = gidx[pt*KNB + lane] + base;
            const float* gp = &pts[(size_t)j*3];
            float dx = gp[0] - cx, dy = gp[1] - cy, dz = gp[2] - cz;
            float dist = sqrtf(fmaf(dx, dx, fmaf(dy, dy, dz*dz)));

            float4 acc = make_float4(-3.0e38f, -3.0e38f, -3.0e38f, -3.0e38f);
#pragma unroll
            for (int k = 0; k < 32; k++) {
                int   jk = __shfl_sync(0xffffffffu, j,    k);
                float dk = __shfl_sync(0xffffffffu, dist, k);
                float4 sv = *(const float4*)&g_s[(size_t)jk*C + c0];
                acc.x = fmaxf(acc.x, fmaf(dk, wd.x, sv.x));
                acc.y = fmaxf(acc.y, fmaf(dk, wd.y, sv.y));
                acc.z = fmaxf(acc.z, fmaf(dk, wd.z, sv.z));
                acc.w = fmaxf(acc.w, fmaf(dk, wd.w, sv.w));
            }
            const float4 f = *(const float4*)&feat[(size_t)pt*C + c0];
            float4 r;
            r.x = fmaxf(acc.x + fmaf(cx, a0.x, fmaf(cy, a1.x, fmaf(cz, a2.x, b2.x))), 0.f) + f.x;
            r.y = fmaxf(acc.y + fmaf(cx, a0.y, fmaf(cy, a1.y, fmaf(cz, a2.y, b2.y))), 0.f) + f.y;
            r.z = fmaxf(acc.z + fmaf(cx, a0.z, fmaf(cy, a1.z, fmaf(cz, a2.z, b2.z))), 0.f) + f.z;
            r.w = fmaxf(acc.w + fmaf(cx, a0.w, fmaf(cy, a1.w, fmaf(cz, a2.w, b2.w))), 0.f) + f.w;
            *(float4*)&a_sm[pl*APAD + c0] = r;
        }
    }
    __syncthreads();

    // ---- Phase B: GEMM res @ w_out (f32x2), 8x8 microtile ----
    const int tx = tid & 15, ty = tid >> 4;
    const int r0 = ty * 8, c0g = tx * 8;

    u64 acc2[8][4];
#pragma unroll
    for (int i = 0; i < 8; i++)
#pragma unroll
        for (int j = 0; j < 4; j++) acc2[i][j] = 0ull;

    for (int kc = 0; kc < 128; kc += 32) {
#pragma unroll
        for (int q = tid; q < 1024; q += 256) {
            int kr = q >> 5, cq = (q & 31) << 2;
            float4 v = *(const float4*)&wout[(size_t)(kc + kr)*C + cq];
            *(float4*)&ws_[kr*C + cq] = v;
        }
        __syncthreads();
#pragma unroll 8
        for (int k = 0; k < 32; k++) {
            ulonglong2 wA = *(const ulonglong2*)&ws_[k*C + c0g];
            ulonglong2 wB = *(const ulonglong2*)&ws_[k*C + c0g + 4];
            u64 w2[4] = { wA.x, wA.y, wB.x, wB.y };
#pragma unroll
            for (int i = 0; i < 8; i++) {
                float a = a_sm[(r0 + i)*APAD + kc + k];
                u64 a2 = pack2(a, a);
#pragma unroll
                for (int j = 0; j < 4; j++)
                    acc2[i][j] = fma2(a2, w2[j], acc2[i][j]);
            }
        }
        __syncthreads();
    }

    // ---- Phase C: +bias into a_sm, row stats, LN + relu, store ----
#pragma unroll
    for (int j = 0; j < 4; j++) {
        float2 bj = *(const float2*)&bout[c0g + 2*j];
#pragma unroll
        for (int i = 0; i < 8; i++) {
            float2 v = unpack2(acc2[i][j]);
            a_sm[(r0 + i)*APAD + c0g + 2*j]     = v.x + bj.x;
            a_sm[(r0 + i)*APAD + c0g + 2*j + 1] = v.y + bj.y;
        }
    }
    __syncthreads();

    if (tid < 128) {
        float sum = 0.f, ss = 0.f;
#pragma unroll 8
        for (int c = 0; c < 128; c += 4) {
            float4 x = *(const float4*)&a_sm[tid*APAD + c];
            sum += x.x + x.y + x.z + x.w;
            ss = fmaf(x.x, x.x, fmaf(x.y, x.y, fmaf(x.z, x.z, fmaf(x.w, x.w, ss))));
        }
        float mu  = sum * (1.f/128.f);
        float var = fmaf(ss, 1.f/128.f, -mu*mu);
        smu[tid] = mu;
        srs[tid] = rsqrtf(var + LN_EPS);
    }
    __syncthreads();

#pragma unroll
    for (int it = 0; it < 16; it++) {
        int idx = tid + it * 256;            // float4 index over 128x32
        int r = idx >> 5, c4 = (idx & 31) << 2;
        float4 x = *(const float4*)&a_sm[r*APAD + c4];
        float4 g = *(const float4*)&lng[c4];
        float4 b = *(const float4*)&lnb[c4];
        float mu = smu[r], rs = srs[r];
        float4 y;
        y.x = fmaxf(fmaf((x.x - mu) * rs, g.x, b.x), 0.f);
        y.y = fmaxf(fmaf((x.y - mu) * rs, g.y, b.y), 0.f);
        y.z = fmaxf(fmaf((x.z - mu) * rs, g.z, b.z), 0.f);
        y.w = fmaxf(fmaf((x.w - mu) * rs, g.w, b.w), 0.f);
        *(float4*)&out[(size_t)(row0 + r)*C + c4] = y;
    }
}

// ---------------------------------------------------------------------------
extern "C" void kernel_launch(void* const* d_in, const int* in_sizes, int n_in,
                              void* d_out, int out_size)
{
    const float* points = (const float*)d_in[0];
    const float* feat   = (const float*)d_in[1];
    const int*   gidx   = (const int*)  d_in[2];
    const float* w_pos  = (const float*)d_in[3];
    const float* b_pos  = (const float*)d_in[4];
    const float* w_gcm  = (const float*)d_in[5];
    const float* b_gcm  = (const float*)d_in[6];
    const float* w_out  = (const float*)d_in[7];
    const float* b_out  = (const float*)d_in[8];
    const float* ln_g   = (const float*)d_in[9];
    const float* ln_b   = (const float*)d_in[10];
    float* out = (float*)d_out;

    cudaFuncSetAttribute(k_fused, cudaFuncAttributeMaxDynamicSharedMemorySize, FUSED_SMEM);

    k_prep   <<<1,        128>>>(w_pos, b_pos, w_gcm, b_gcm);
    k_gemm_s <<<MTOT/128, 256>>>(feat, w_gcm, points);
    k_fused  <<<MTOT/128, 256, FUSED_SMEM>>>(points, feat, gidx,
                                             w_out, b_out, ln_g, ln_b, out);
}

// round 3
// speedup vs baseline: 1.5651x; 1.2779x over previous
#include <cuda_runtime.h>
#include <math.h>

#define BATCH 2
#define NPTS  16384
#define KNB   32
#define C     128
#define MTOT  (BATCH*NPTS)   // 32768
#define LN_EPS 1e-5f

// scratch (device globals; no runtime allocation)
__device__ float g_s  [(size_t)MTOT*C];   // 16 MB
__device__ float g_A  [3*C];
__device__ float g_Bm [3*C];
__device__ float g_wd [C];
__device__ float g_b2 [C];

typedef unsigned long long u64;

__device__ __forceinline__ u64 pack2(float x, float y) {
    u64 r; asm("mov.b64 %0,{%1,%2};" : "=l"(r) : "f"(x), "f"(y)); return r;
}
__device__ __forceinline__ u64 fma2(u64 a, u64 b, u64 c) {
    u64 d; asm("fma.rn.f32x2 %0,%1,%2,%3;" : "=l"(d) : "l"(a), "l"(b), "l"(c)); return d;
}
__device__ __forceinline__ float2 unpack2(u64 v) {
    float2 f; asm("mov.b64 {%0,%1},%2;" : "=f"(f.x), "=f"(f.y) : "l"(v)); return f;
}

// ---------------------------------------------------------------------------
// K1: fold w_pos through w_gcm — parallel version.
// 128 CTAs (one per output channel c), 128 threads (one per k-index j).
// pg[i] = sum_j w_pos[i][j] * w_gcm[j][c]  via warp-shuffle reduction.
// ---------------------------------------------------------------------------
__global__ __launch_bounds__(128) void k_prep(
    const float* __restrict__ w_pos, const float* __restrict__ b_pos,
    const float* __restrict__ w_gcm, const float* __restrict__ b_gcm)
{
    const int c = blockIdx.x;      // channel
    const int j = threadIdx.x;     // k index
    const int wid  = j >> 5;
    const int lane = j & 31;

    __shared__ float part[11][4];

    const float wc = w_gcm[(size_t)j*C + c];

    float v[11];
#pragma unroll
    for (int i = 0; i < 10; i++) v[i] = w_pos[i*C + j] * wc;
    v[10] = b_pos[j] * wc;

#pragma unroll
    for (int i = 0; i < 11; i++) {
        float x = v[i];
#pragma unroll
        for (int s = 16; s > 0; s >>= 1)
            x += __shfl_xor_sync(0xffffffffu, x, s);
        if (lane == 0) part[i][wid] = x;
    }
    __syncthreads();

    if (j == 0) {
        float pg[11];
#pragma unroll
        for (int i = 0; i < 11; i++)
            pg[i] = part[i][0] + part[i][1] + part[i][2] + part[i][3];
#pragma unroll
        for (int d = 0; d < 3; d++) {
            g_A [d*C + c] = pg[d]     - pg[6 + d];
            g_Bm[d*C + c] = pg[3 + d] + pg[6 + d];
        }
        g_wd[c] = pg[9];
        g_b2[c] = pg[10] + b_gcm[c];
    }
}

// ---------------------------------------------------------------------------
// K2: g_s[m] = features[m] @ w_gcm + points[m]·Bm   (f32x2 packed FMA)
// 128x128 CTA tile, 256 threads, 8x8 microtile, KC=32 chunks.
// ---------------------------------------------------------------------------
__global__ __launch_bounds__(256, 2) void k_gemm_s(
    const float* __restrict__ feat, const float* __restrict__ wg,
    const float* __restrict__ pts)
{
    __shared__ float as[128][36];
    __shared__ float ws[32][128];
    const int tid = threadIdx.x;
    const int tx = tid & 15, ty = tid >> 4;
    const int row0 = blockIdx.x * 128;
    const int r0 = ty * 8, c0 = tx * 8;

    u64 acc2[8][4];
#pragma unroll
    for (int i = 0; i < 8; i++)
#pragma unroll
        for (int j = 0; j < 4; j++) acc2[i][j] = 0ull;

    for (int kc = 0; kc < 128; kc += 32) {
#pragma unroll
        for (int q = tid; q < 1024; q += 256) {
            int row = q >> 3, kq = (q & 7) << 2;
            float4 v = *(const float4*)&feat[(size_t)(row0 + row)*C + kc + kq];
            *(float4*)&as[row][kq] = v;
        }
#pragma unroll
        for (int q = tid; q < 1024; q += 256) {
            int kr = q >> 5, cq = (q & 31) << 2;
            float4 v = *(const float4*)&wg[(size_t)(kc + kr)*C + cq];
            *(float4*)&ws[kr][cq] = v;
        }
        __syncthreads();
#pragma unroll 8
        for (int k = 0; k < 32; k++) {
            ulonglong2 wA = *(const ulonglong2*)&ws[k][c0];
            ulonglong2 wB = *(const ulonglong2*)&ws[k][c0 + 4];
            u64 w2[4] = { wA.x, wA.y, wB.x, wB.y };
#pragma unroll
            for (int i = 0; i < 8; i++) {
                float a = as[r0 + i][k];
                u64 a2 = pack2(a, a);
#pragma unroll
                for (int j = 0; j < 4; j++)
                    acc2[i][j] = fma2(a2, w2[j], acc2[i][j]);
            }
        }
        __syncthreads();
    }

    // epilogue: + points·Bm, store
    float bm[3][8];
#pragma unroll
    for (int d = 0; d < 3; d++)
#pragma unroll
        for (int j = 0; j < 8; j++) bm[d][j] = g_Bm[d*C + c0 + j];

#pragma unroll
    for (int i = 0; i < 8; i++) {
        int r = row0 + r0 + i;
        float px = pts[r*3 + 0], py = pts[r*3 + 1], pz = pts[r*3 + 2];
        float acc[8];
#pragma unroll
        for (int j = 0; j < 4; j++) {
            float2 v = unpack2(acc2[i][j]);
            acc[2*j] = v.x; acc[2*j + 1] = v.y;
        }
#pragma unroll
        for (int j = 0; j < 8; j++)
            acc[j] = fmaf(px, bm[0][j], fmaf(py, bm[1][j], fmaf(pz, bm[2][j], acc[j])));
        float4 o0 = make_float4(acc[0], acc[1], acc[2], acc[3]);
        float4 o1 = make_float4(acc[4], acc[5], acc[6], acc[7]);
        *(float4*)&g_s[(size_t)r*C + c0]     = o0;
        *(float4*)&g_s[(size_t)r*C + c0 + 4] = o1;
    }
}

// ---------------------------------------------------------------------------
// K3 (fused): per-CTA pool 128 rows into smem, then res @ w_out GEMM with
// fused bias + LayerNorm + relu epilogue.
// Dynamic smem: a[128][132] + ws[32][128] + mu[128] + rs[128] = 84992 B.
// ---------------------------------------------------------------------------
#define APAD 132
#define FUSED_SMEM ((128*APAD + 32*128 + 256) * 4)

__global__ __launch_bounds__(256, 2) void k_fused(
    const float* __restrict__ pts,  const float* __restrict__ feat,
    const int*   __restrict__ gidx,
    const float* __restrict__ wout, const float* __restrict__ bout,
    const float* __restrict__ lng,  const float* __restrict__ lnb,
    float* __restrict__ out)
{
    extern __shared__ float sh[];
    float* a_sm = sh;                    // [128][APAD]
    float* ws_  = sh + 128*APAD;         // [32][128]
    float* smu  = ws_ + 32*128;          // [128]
    float* srs  = smu + 128;             // [128]

    const int tid  = threadIdx.x;
    const int wid  = tid >> 5;
    const int lane = tid & 31;
    const int row0 = blockIdx.x * 128;

    // ---- Phase A: pool 128 points into a_sm (warp w handles 16 points) ----
    {
        const int c0 = lane << 2;
        const float4 wd = *(const float4*)&g_wd[c0];
        const float4 a0 = *(const float4*)&g_A[c0];
        const float4 a1 = *(const float4*)&g_A[C + c0];
        const float4 a2 = *(const float4*)&g_A[2*C + c0];
        const float4 b2 = *(const float4*)&g_b2[c0];

        for (int t = 0; t < 16; t++) {
            const int pl = wid * 16 + t;        // local row
            const int pt = row0 + pl;
            const int base = (pt >> 14) << 14;  // batch base row

            const float cx = pts[pt*3 + 0], cy = pts[pt*3 + 1], cz = pts[pt*3 + 2];
            int j = gidx[pt*KNB + lane] + base;
            const float* gp = &pts[(size_t)j*3];
            float dx = gp[0] - cx, dy = gp[1] - cy, dz = gp[2] - cz;
            float dist = sqrtf(fmaf(dx, dx, fmaf(dy, dy, dz*dz)));

            float4 acc = make_float4(-3.0e38f, -3.0e38f, -3.0e38f, -3.0e38f);
#pragma unroll
            for (int k = 0; k < 32; k++) {
                int   jk = __shfl_sync(0xffffffffu, j,    k);
                float dk = __shfl_sync(0xffffffffu, dist, k);
                float4 sv = *(const float4*)&g_s[(size_t)jk*C + c0];
                acc.x = fmaxf(acc.x, fmaf(dk, wd.x, sv.x));
                acc.y = fmaxf(acc.y, fmaf(dk, wd.y, sv.y));
                acc.z = fmaxf(acc.z, fmaf(dk, wd.z, sv.z));
                acc.w = fmaxf(acc.w, fmaf(dk, wd.w, sv.w));
            }
            const float4 f = *(const float4*)&feat[(size_t)pt*C + c0];
            float4 r;
            r.x = fmaxf(acc.x + fmaf(cx, a0.x, fmaf(cy, a1.x, fmaf(cz, a2.x, b2.x))), 0.f) + f.x;
            r.y = fmaxf(acc.y + fmaf(cx, a0.y, fmaf(cy, a1.y, fmaf(cz, a2.y, b2.y))), 0.f) + f.y;
            r.z = fmaxf(acc.z + fmaf(cx, a0.z, fmaf(cy, a1.z, fmaf(cz, a2.z, b2.z))), 0.f) + f.z;
            r.w = fmaxf(acc.w + fmaf(cx, a0.w, fmaf(cy, a1.w, fmaf(cz, a2.w, b2.w))), 0.f) + f.w;
            *(float4*)&a_sm[pl*APAD + c0] = r;
        }
    }
    __syncthreads();

    // ---- Phase B: GEMM res @ w_out (f32x2), 8x8 microtile ----
    const int tx = tid & 15, ty = tid >> 4;
    const int r0 = ty * 8, c0g = tx * 8;

    u64 acc2[8][4];
#pragma unroll
    for (int i = 0; i < 8; i++)
#pragma unroll
        for (int j = 0; j < 4; j++) acc2[i][j] = 0ull;

    for (int kc = 0; kc < 128; kc += 32) {
#pragma unroll
        for (int q = tid; q < 1024; q += 256) {
            int kr = q >> 5, cq = (q & 31) << 2;
            float4 v = *(const float4*)&wout[(size_t)(kc + kr)*C + cq];
            *(float4*)&ws_[kr*C + cq] = v;
        }
        __syncthreads();
#pragma unroll 8
        for (int k = 0; k < 32; k++) {
            ulonglong2 wA = *(const ulonglong2*)&ws_[k*C + c0g];
            ulonglong2 wB = *(const ulonglong2*)&ws_[k*C + c0g + 4];
            u64 w2[4] = { wA.x, wA.y, wB.x, wB.y };
#pragma unroll
            for (int i = 0; i < 8; i++) {
                float a = a_sm[(r0 + i)*APAD + kc + k];
                u64 a2 = pack2(a, a);
#pragma unroll
                for (int j = 0; j < 4; j++)
                    acc2[i][j] = fma2(a2, w2[j], acc2[i][j]);
            }
        }
        __syncthreads();
    }

    // ---- Phase C: +bias into a_sm, row stats, LN + relu, store ----
#pragma unroll
    for (int j = 0; j < 4; j++) {
        float2 bj = *(const float2*)&bout[c0g + 2*j];
#pragma unroll
        for (int i = 0; i < 8; i++) {
            float2 v = unpack2(acc2[i][j]);
            a_sm[(r0 + i)*APAD + c0g + 2*j]     = v.x + bj.x;
            a_sm[(r0 + i)*APAD + c0g + 2*j + 1] = v.y + bj.y;
        }
    }
    __syncthreads();

    if (tid < 128) {
        float sum = 0.f, ss = 0.f;
#pragma unroll 8
        for (int c = 0; c < 128; c += 4) {
            float4 x = *(const float4*)&a_sm[tid*APAD + c];
            sum += x.x + x.y + x.z + x.w;
            ss = fmaf(x.x, x.x, fmaf(x.y, x.y, fmaf(x.z, x.z, fmaf(x.w, x.w, ss))));
        }
        float mu  = sum * (1.f/128.f);
        float var = fmaf(ss, 1.f/128.f, -mu*mu);
        smu[tid] = mu;
        srs[tid] = rsqrtf(var + LN_EPS);
    }
    __syncthreads();

#pragma unroll
    for (int it = 0; it < 16; it++) {
        int idx = tid + it * 256;            // float4 index over 128x32
        int r = idx >> 5, c4 = (idx & 31) << 2;
        float4 x = *(const float4*)&a_sm[r*APAD + c4];
        float4 g = *(const float4*)&lng[c4];
        float4 b = *(const float4*)&lnb[c4];
        float mu = smu[r], rs = srs[r];
        float4 y;
        y.x = fmaxf(fmaf((x.x - mu) * rs, g.x, b.x), 0.f);
        y.y = fmaxf(fmaf((x.y - mu) * rs, g.y, b.y), 0.f);
        y.z = fmaxf(fmaf((x.z - mu) * rs, g.z, b.z), 0.f);
        y.w = fmaxf(fmaf((x.w - mu) * rs, g.w, b.w), 0.f);
        *(float4*)&out[(size_t)(row0 + r)*C + c4] = y;
    }
}

// ---------------------------------------------------------------------------
extern "C" void kernel_launch(void* const* d_in, const int* in_sizes, int n_in,
                              void* d_out, int out_size)
{
    const float* points = (const float*)d_in[0];
    const float* feat   = (const float*)d_in[1];
    const int*   gidx   = (const int*)  d_in[2];
    const float* w_pos  = (const float*)d_in[3];
    const float* b_pos  = (const float*)d_in[4];
    const float* w_gcm  = (const float*)d_in[5];
    const float* b_gcm  = (const float*)d_in[6];
    const float* w_out  = (const float*)d_in[7];
    const float* b_out  = (const float*)d_in[8];
    const float* ln_g   = (const float*)d_in[9];
    const float* ln_b   = (const float*)d_in[10];
    float* out = (float*)d_out;

    cudaFuncSetAttribute(k_fused, cudaFuncAttributeMaxDynamicSharedMemorySize, FUSED_SMEM);

    k_prep   <<<C,        128>>>(w_pos, b_pos, w_gcm, b_gcm);
    k_gemm_s <<<MTOT/128, 256>>>(feat, w_gcm, points);
    k_fused  <<<MTOT/128, 256, FUSED_SMEM>>>(points, feat, gidx,
                                             w_out, b_out, ln_g, ln_b, out);
}

// round 4
// speedup vs baseline: 1.6672x; 1.0652x over previous
#include <cuda_runtime.h>
#include <cuda_fp16.h>
#include <math.h>

#define BATCH 2
#define NPTS  16384
#define KNB   32
#define C     128
#define MTOT  (BATCH*NPTS)   // 32768
#define LN_EPS 1e-5f

// scratch (device globals; no runtime allocation)
__device__ __half g_h [(size_t)MTOT*C];   // 8 MB, s in fp16
__device__ float  g_A [3*C];
__device__ float  g_Bm[3*C];
__device__ float  g_wd[C];
__device__ float  g_b2[C];

typedef unsigned long long u64;

__device__ __forceinline__ u64 pack2(float x, float y) {
    u64 r; asm("mov.b64 %0,{%1,%2};" : "=l"(r) : "f"(x), "f"(y)); return r;
}
__device__ __forceinline__ u64 fma2(u64 a, u64 b, u64 c) {
    u64 d; asm("fma.rn.f32x2 %0,%1,%2,%3;" : "=l"(d) : "l"(a), "l"(b), "l"(c)); return d;
}
__device__ __forceinline__ float2 unpack2(u64 v) {
    float2 f; asm("mov.b64 {%0,%1},%2;" : "=f"(f.x), "=f"(f.y) : "l"(v)); return f;
}

// ---------------------------------------------------------------------------
// K1: fold w_pos through w_gcm — 128 CTAs (one per channel), shuffle reduce.
// ---------------------------------------------------------------------------
__global__ __launch_bounds__(128) void k_prep(
    const float* __restrict__ w_pos, const float* __restrict__ b_pos,
    const float* __restrict__ w_gcm, const float* __restrict__ b_gcm)
{
    const int c = blockIdx.x;
    const int j = threadIdx.x;
    const int wid  = j >> 5;
    const int lane = j & 31;

    __shared__ float part[11][4];

    const float wc = w_gcm[(size_t)j*C + c];

    float v[11];
#pragma unroll
    for (int i = 0; i < 10; i++) v[i] = w_pos[i*C + j] * wc;
    v[10] = b_pos[j] * wc;

#pragma unroll
    for (int i = 0; i < 11; i++) {
        float x = v[i];
#pragma unroll
        for (int s = 16; s > 0; s >>= 1)
            x += __shfl_xor_sync(0xffffffffu, x, s);
        if (lane == 0) part[i][wid] = x;
    }
    __syncthreads();

    if (j == 0) {
        float pg[11];
#pragma unroll
        for (int i = 0; i < 11; i++)
            pg[i] = part[i][0] + part[i][1] + part[i][2] + part[i][3];
#pragma unroll
        for (int d = 0; d < 3; d++) {
            g_A [d*C + c] = pg[d]     - pg[6 + d];
            g_Bm[d*C + c] = pg[3 + d] + pg[6 + d];
        }
        g_wd[c] = pg[9];
        g_b2[c] = pg[10] + b_gcm[c];
    }
}

// ---------------------------------------------------------------------------
// K2: s[m] = features[m] @ w_gcm + points[m]·Bm  -> fp16 store.
// 128x128 CTA tile, 256 threads, 8x8 microtile. A-tile transposed (k-major).
// ---------------------------------------------------------------------------
__global__ __launch_bounds__(256, 2) void k_gemm_s(
    const float* __restrict__ feat, const float* __restrict__ wg,
    const float* __restrict__ pts)
{
    __shared__ float as_t[32*132];   // [k][row], pad 132 (16B-aligned row pitch)
    __shared__ float ws[32][128];
    const int tid = threadIdx.x;
    const int tx = tid & 15, ty = tid >> 4;
    const int row0 = blockIdx.x * 128;
    const int r0 = ty * 8, c0 = tx * 8;

    u64 acc2[8][4];
#pragma unroll
    for (int i = 0; i < 8; i++)
#pragma unroll
        for (int j = 0; j < 4; j++) acc2[i][j] = 0ull;

    for (int kc = 0; kc < 128; kc += 32) {
#pragma unroll
        for (int q = tid; q < 1024; q += 256) {
            int row = q >> 3, kq = (q & 7) << 2;
            float4 v = *(const float4*)&feat[(size_t)(row0 + row)*C + kc + kq];
            as_t[(kq + 0)*132 + row] = v.x;
            as_t[(kq + 1)*132 + row] = v.y;
            as_t[(kq + 2)*132 + row] = v.z;
            as_t[(kq + 3)*132 + row] = v.w;
        }
#pragma unroll
        for (int q = tid; q < 1024; q += 256) {
            int kr = q >> 5, cq = (q & 31) << 2;
            float4 v = *(const float4*)&wg[(size_t)(kc + kr)*C + cq];
            *(float4*)&ws[kr][cq] = v;
        }
        __syncthreads();
#pragma unroll 8
        for (int k = 0; k < 32; k++) {
            float4 av0 = *(const float4*)&as_t[k*132 + r0];
            float4 av1 = *(const float4*)&as_t[k*132 + r0 + 4];
            float a[8] = { av0.x, av0.y, av0.z, av0.w, av1.x, av1.y, av1.z, av1.w };
            ulonglong2 wA = *(const ulonglong2*)&ws[k][c0];
            ulonglong2 wB = *(const ulonglong2*)&ws[k][c0 + 4];
            u64 w2[4] = { wA.x, wA.y, wB.x, wB.y };
#pragma unroll
            for (int i = 0; i < 8; i++) {
                u64 a2 = pack2(a[i], a[i]);
#pragma unroll
                for (int j = 0; j < 4; j++)
                    acc2[i][j] = fma2(a2, w2[j], acc2[i][j]);
            }
        }
        __syncthreads();
    }

    // epilogue: + points·Bm, convert to fp16, store 16B per row-slice
    float bm[3][8];
#pragma unroll
    for (int d = 0; d < 3; d++)
#pragma unroll
        for (int j = 0; j < 8; j++) bm[d][j] = g_Bm[d*C + c0 + j];

#pragma unroll
    for (int i = 0; i < 8; i++) {
        int r = row0 + r0 + i;
        float px = pts[r*3 + 0], py = pts[r*3 + 1], pz = pts[r*3 + 2];
        float acc[8];
#pragma unroll
        for (int j = 0; j < 4; j++) {
            float2 v = unpack2(acc2[i][j]);
            acc[2*j] = v.x; acc[2*j + 1] = v.y;
        }
#pragma unroll
        for (int j = 0; j < 8; j++)
            acc[j] = fmaf(px, bm[0][j], fmaf(py, bm[1][j], fmaf(pz, bm[2][j], acc[j])));

        __half2 h0 = __floats2half2_rn(acc[0], acc[1]);
        __half2 h1 = __floats2half2_rn(acc[2], acc[3]);
        __half2 h2 = __floats2half2_rn(acc[4], acc[5]);
        __half2 h3 = __floats2half2_rn(acc[6], acc[7]);
        uint4 o;
        o.x = *(unsigned*)&h0; o.y = *(unsigned*)&h1;
        o.z = *(unsigned*)&h2; o.w = *(unsigned*)&h3;
        *(uint4*)&g_h[(size_t)r*C + c0] = o;
    }
}

// ---------------------------------------------------------------------------
// K3 (fused): per-CTA pool 128 rows into smem (fp16 gathers), then
// res @ w_out GEMM with fused bias + LayerNorm + relu epilogue.
// ---------------------------------------------------------------------------
#define APAD 132
#define FUSED_SMEM ((128*APAD + 32*128 + 256) * 4)

__global__ __launch_bounds__(256, 2) void k_fused(
    const float* __restrict__ pts,  const float* __restrict__ feat,
    const int*   __restrict__ gidx,
    const float* __restrict__ wout, const float* __restrict__ bout,
    const float* __restrict__ lng,  const float* __restrict__ lnb,
    float* __restrict__ out)
{
    extern __shared__ float sh[];
    float* a_sm = sh;                    // [128][APAD]
    float* ws_  = sh + 128*APAD;         // [32][128]
    float* smu  = ws_ + 32*128;          // [128]
    float* srs  = smu + 128;             // [128]

    const int tid  = threadIdx.x;
    const int wid  = tid >> 5;
    const int lane = tid & 31;
    const int row0 = blockIdx.x * 128;

    // ---- Phase A: pool 128 points into a_sm (warp handles 16 points) ----
    {
        const int c0 = lane << 2;
        const float4 wd = *(const float4*)&g_wd[c0];
        const float4 a0 = *(const float4*)&g_A[c0];
        const float4 a1 = *(const float4*)&g_A[C + c0];
        const float4 a2 = *(const float4*)&g_A[2*C + c0];
        const float4 b2 = *(const float4*)&g_b2[c0];

        for (int t = 0; t < 16; t++) {
            const int pl = wid * 16 + t;
            const int pt = row0 + pl;
            const int base = (pt >> 14) << 14;

            const float cx = pts[pt*3 + 0], cy = pts[pt*3 + 1], cz = pts[pt*3 + 2];
            int j = gidx[pt*KNB + lane] + base;
            const float* gp = &pts[(size_t)j*3];
            float dx = gp[0] - cx, dy = gp[1] - cy, dz = gp[2] - cz;
            float dist = sqrtf(fmaf(dx, dx, fmaf(dy, dy, dz*dz)));

            float4 acc = make_float4(-3.0e38f, -3.0e38f, -3.0e38f, -3.0e38f);
#pragma unroll
            for (int k = 0; k < 32; k++) {
                int   jk = __shfl_sync(0xffffffffu, j,    k);
                float dk = __shfl_sync(0xffffffffu, dist, k);
                uint2 raw = *(const uint2*)&g_h[(size_t)jk*C + c0];
                float2 s01 = __half22float2(*(__half2*)&raw.x);
                float2 s23 = __half22float2(*(__half2*)&raw.y);
                acc.x = fmaxf(acc.x, fmaf(dk, wd.x, s01.x));
                acc.y = fmaxf(acc.y, fmaf(dk, wd.y, s01.y));
                acc.z = fmaxf(acc.z, fmaf(dk, wd.z, s23.x));
                acc.w = fmaxf(acc.w, fmaf(dk, wd.w, s23.y));
            }
            const float4 f = *(const float4*)&feat[(size_t)pt*C + c0];
            float4 r;
            r.x = fmaxf(acc.x + fmaf(cx, a0.x, fmaf(cy, a1.x, fmaf(cz, a2.x, b2.x))), 0.f) + f.x;
            r.y = fmaxf(acc.y + fmaf(cx, a0.y, fmaf(cy, a1.y, fmaf(cz, a2.y, b2.y))), 0.f) + f.y;
            r.z = fmaxf(acc.z + fmaf(cx, a0.z, fmaf(cy, a1.z, fmaf(cz, a2.z, b2.z))), 0.f) + f.z;
            r.w = fmaxf(acc.w + fmaf(cx, a0.w, fmaf(cy, a1.w, fmaf(cz, a2.w, b2.w))), 0.f) + f.w;
            *(float4*)&a_sm[pl*APAD + c0] = r;
        }
    }
    __syncthreads();

    // ---- Phase B: GEMM res @ w_out (f32x2), 8x8 microtile ----
    const int tx = tid & 15, ty = tid >> 4;
    const int r0 = ty * 8, c0g = tx * 8;

    u64 acc2[8][4];
#pragma unroll
    for (int i = 0; i < 8; i++)
#pragma unroll
        for (int j = 0; j < 4; j++) acc2[i][j] = 0ull;

    for (int kc = 0; kc < 128; kc += 32) {
#pragma unroll
        for (int q = tid; q < 1024; q += 256) {
            int kr = q >> 5, cq = (q & 31) << 2;
            float4 v = *(const float4*)&wout[(size_t)(kc + kr)*C + cq];
            *(float4*)&ws_[kr*C + cq] = v;
        }
        __syncthreads();
#pragma unroll 8
        for (int k = 0; k < 32; k++) {
            ulonglong2 wA = *(const ulonglong2*)&ws_[k*C + c0g];
            ulonglong2 wB = *(const ulonglong2*)&ws_[k*C + c0g + 4];
            u64 w2[4] = { wA.x, wA.y, wB.x, wB.y };
#pragma unroll
            for (int i = 0; i < 8; i++) {
                float a = a_sm[(r0 + i)*APAD + kc + k];
                u64 a2 = pack2(a, a);
#pragma unroll
                for (int j = 0; j < 4; j++)
                    acc2[i][j] = fma2(a2, w2[j], acc2[i][j]);
            }
        }
        __syncthreads();
    }

    // ---- Phase C: +bias into a_sm, row stats, LN + relu, store ----
#pragma unroll
    for (int j = 0; j < 4; j++) {
        float2 bj = *(const float2*)&bout[c0g + 2*j];
#pragma unroll
        for (int i = 0; i < 8; i++) {
            float2 v = unpack2(acc2[i][j]);
            a_sm[(r0 + i)*APAD + c0g + 2*j]     = v.x + bj.x;
            a_sm[(r0 + i)*APAD + c0g + 2*j + 1] = v.y + bj.y;
        }
    }
    __syncthreads();

    if (tid < 128) {
        float sum = 0.f, ss = 0.f;
#pragma unroll 8
        for (int c = 0; c < 128; c += 4) {
            float4 x = *(const float4*)&a_sm[tid*APAD + c];
            sum += x.x + x.y + x.z + x.w;
            ss = fmaf(x.x, x.x, fmaf(x.y, x.y, fmaf(x.z, x.z, fmaf(x.w, x.w, ss))));
        }
        float mu  = sum * (1.f/128.f);
        float var = fmaf(ss, 1.f/128.f, -mu*mu);
        smu[tid] = mu;
        srs[tid] = rsqrtf(var + LN_EPS);
    }
    __syncthreads();

#pragma unroll
    for (int it = 0; it < 16; it++) {
        int idx = tid + it * 256;
        int r = idx >> 5, c4 = (idx & 31) << 2;
        float4 x = *(const float4*)&a_sm[r*APAD + c4];
        float4 g = *(const float4*)&lng[c4];
        float4 b = *(const float4*)&lnb[c4];
        float mu = smu[r], rs = srs[r];
        float4 y;
        y.x = fmaxf(fmaf((x.x - mu) * rs, g.x, b.x), 0.f);
        y.y = fmaxf(fmaf((x.y - mu) * rs, g.y, b.y), 0.f);
        y.z = fmaxf(fmaf((x.z - mu) * rs, g.z, b.z), 0.f);
        y.w = fmaxf(fmaf((x.w - mu) * rs, g.w, b.w), 0.f);
        *(float4*)&out[(size_t)(row0 + r)*C + c4] = y;
    }
}

// ---------------------------------------------------------------------------
extern "C" void kernel_launch(void* const* d_in, const int* in_sizes, int n_in,
                              void* d_out, int out_size)
{
    const float* points = (const float*)d_in[0];
    const float* feat   = (const float*)d_in[1];
    const int*   gidx   = (const int*)  d_in[2];
    const float* w_pos  = (const float*)d_in[3];
    const float* b_pos  = (const float*)d_in[4];
    const float* w_gcm  = (const float*)d_in[5];
    const float* b_gcm  = (const float*)d_in[6];
    const float* w_out  = (const float*)d_in[7];
    const float* b_out  = (const float*)d_in[8];
    const float* ln_g   = (const float*)d_in[9];
    const float* ln_b   = (const float*)d_in[10];
    float* out = (float*)d_out;

    cudaFuncSetAttribute(k_fused, cudaFuncAttributeMaxDynamicSharedMemorySize, FUSED_SMEM);

    k_prep   <<<C,        128>>>(w_pos, b_pos, w_gcm, b_gcm);
    k_gemm_s <<<MTOT/128, 256>>>(feat, w_gcm, points);
    k_fused  <<<MTOT/128, 256, FUSED_SMEM>>>(points, feat, gidx,
                                             w_out, b_out, ln_g, ln_b, out);
}

// round 6
// speedup vs baseline: 2.1138x; 1.2678x over previous
#include <cuda_runtime.h>
#include <cuda_fp16.h>
#include <mma.h>
#include <math.h>
#include <stdint.h>

using namespace nvcuda;

#define BATCH 2
#define NPTS  16384
#define KNB   32
#define C     128
#define MTOT  (BATCH*NPTS)   // 32768
#define LN_EPS 1e-5f

// scratch (device globals; no runtime allocation)
__device__ __half g_h [(size_t)MTOT*C];   // 8 MB, s in fp16
__device__ __half g_bh[(size_t)C*C];      // w_gcm in fp16, [k][n] (row-major B)
__device__ float  g_A [3*C];
__device__ float  g_Bm[3*C];
__device__ float  g_wd[C];
__device__ float  g_b2[C];

typedef unsigned long long u64;

__device__ __forceinline__ u64 pack2(float x, float y) {
    u64 r; asm("mov.b64 %0,{%1,%2};" : "=l"(r) : "f"(x), "f"(y)); return r;
}
__device__ __forceinline__ u64 fma2(u64 a, u64 b, u64 c) {
    u64 d; asm("fma.rn.f32x2 %0,%1,%2,%3;" : "=l"(d) : "l"(a), "l"(b), "l"(c)); return d;
}
__device__ __forceinline__ float2 unpack2(u64 v) {
    float2 f; asm("mov.b64 {%0,%1},%2;" : "=f"(f.x), "=f"(f.y) : "l"(v)); return f;
}

// ---------------------------------------------------------------------------
// K1: fold w_pos through w_gcm — 128 CTAs (one per channel), shuffle reduce.
// Also emits g_bh[k][n] = fp16(w_gcm[k][n]) for the wmma GEMM.
// ---------------------------------------------------------------------------
__global__ __launch_bounds__(128) void k_prep(
    const float* __restrict__ w_pos, const float* __restrict__ b_pos,
    const float* __restrict__ w_gcm, const float* __restrict__ b_gcm)
{
    const int c = blockIdx.x;
    const int j = threadIdx.x;
    const int wid  = j >> 5;
    const int lane = j & 31;

    __shared__ float part[11][4];

    const float wc = w_gcm[(size_t)j*C + c];
    g_bh[(size_t)j*C + c] = __float2half_rn(wc);

    float v[11];
#pragma unroll
    for (int i = 0; i < 10; i++) v[i] = w_pos[i*C + j] * wc;
    v[10] = b_pos[j] * wc;

#pragma unroll
    for (int i = 0; i < 11; i++) {
        float x = v[i];
#pragma unroll
        for (int s = 16; s > 0; s >>= 1)
            x += __shfl_xor_sync(0xffffffffu, x, s);
        if (lane == 0) part[i][wid] = x;
    }
    __syncthreads();

    if (j == 0) {
        float pg[11];
#pragma unroll
        for (int i = 0; i < 11; i++)
            pg[i] = part[i][0] + part[i][1] + part[i][2] + part[i][3];
#pragma unroll
        for (int d = 0; d < 3; d++) {
            g_A [d*C + c] = pg[d]     - pg[6 + d];
            g_Bm[d*C + c] = pg[3 + d] + pg[6 + d];
        }
        g_wd[c] = pg[9];
        g_b2[c] = pg[10] + b_gcm[c];
    }
}

// ---------------------------------------------------------------------------
// K2 (wmma tensor core): s = feat @ w_gcm + pts·Bm -> fp16 g_h.
// CTA: 128x128 tile, 256 threads = 8 warps in 4x2; each warp 32x64
// (2x4 wmma 16x16x16 accum frags). A/B staged fp16 in smem; epilogue via
// fp32 smem re-use of the same dynamic buffer.
// ---------------------------------------------------------------------------
#define ALD 136                     // a/b smem pitch in halves (272 B)
#define CLD 132                     // c  smem pitch in floats (528 B)
#define WMMA_SMEM (2 * 128 * ALD * 2)        // 69632 B (stage phase)
// epi phase uses: float c[128][132] = 67584 B + bm 1536 B = 69120 B  (fits)

__global__ __launch_bounds__(256) void k_gemm_s(
    const float* __restrict__ feat, const float* __restrict__ pts)
{
    extern __shared__ char dyn[];
    __half* a_sm = (__half*)dyn;                    // [128][ALD]
    __half* b_sm = (__half*)dyn + 128*ALD;          // [128][ALD]

    const int tid  = threadIdx.x;
    const int wid  = tid >> 5;
    const int row0 = blockIdx.x * 128;

    // stage A: feat fp32 -> fp16 smem
#pragma unroll
    for (int it = 0; it < 16; it++) {
        int idx = tid + it * 256;            // 4096 float4s over 128x128
        int r = idx >> 5, c4 = (idx & 31) << 2;
        float4 v = *(const float4*)&feat[(size_t)(row0 + r)*C + c4];
        __half2 h0 = __floats2half2_rn(v.x, v.y);
        __half2 h1 = __floats2half2_rn(v.z, v.w);
        uint2 o; o.x = *(unsigned*)&h0; o.y = *(unsigned*)&h1;
        *(uint2*)&a_sm[r*ALD + c4] = o;
    }
    // stage B: g_bh fp16 [k][n]
#pragma unroll
    for (int it = 0; it < 8; it++) {
        int idx = tid + it * 256;            // 2048 uint4s over 128x128 halves
        int k = idx >> 4, c8 = (idx & 15) << 3;
        uint4 v = *(const uint4*)&g_bh[(size_t)k*C + c8];
        *(uint4*)&b_sm[k*ALD + c8] = v;
    }
    __syncthreads();

    const int wm = wid >> 1;     // 0..3 -> rows 32*wm
    const int wn = wid & 1;      // 0..1 -> cols 64*wn

    wmma::fragment<wmma::accumulator, 16, 16, 16, float> acc[2][4];
#pragma unroll
    for (int i = 0; i < 2; i++)
#pragma unroll
        for (int j = 0; j < 4; j++) wmma::fill_fragment(acc[i][j], 0.f);

#pragma unroll
    for (int kk = 0; kk < 8; kk++) {
        wmma::fragment<wmma::matrix_a, 16, 16, 16, __half, wmma::row_major> af[2];
        wmma::fragment<wmma::matrix_b, 16, 16, 16, __half, wmma::row_major> bf[4];
#pragma unroll
        for (int i = 0; i < 2; i++)
            wmma::load_matrix_sync(af[i], &a_sm[(wm*32 + i*16)*ALD + kk*16], ALD);
#pragma unroll
        for (int j = 0; j < 4; j++)
            wmma::load_matrix_sync(bf[j], &b_sm[(kk*16)*ALD + wn*64 + j*16], ALD);
#pragma unroll
        for (int i = 0; i < 2; i++)
#pragma unroll
            for (int j = 0; j < 4; j++)
                wmma::mma_sync(acc[i][j], af[i], bf[j], acc[i][j]);
    }
    __syncthreads();

    // epilogue: frags -> fp32 smem, + pts·Bm, fp16 store
    float* c_sm = (float*)dyn;                       // [128][CLD]
    float* bm_s = (float*)dyn + 128*CLD;             // [3*C]
    for (int i = tid; i < 3*C; i += 256) bm_s[i] = g_Bm[i];

#pragma unroll
    for (int i = 0; i < 2; i++)
#pragma unroll
        for (int j = 0; j < 4; j++)
            wmma::store_matrix_sync(&c_sm[(wm*32 + i*16)*CLD + wn*64 + j*16],
                                    acc[i][j], CLD, wmma::mem_row_major);
    __syncthreads();

#pragma unroll
    for (int it = 0; it < 16; it++) {
        int idx = tid + it * 256;
        int r = idx >> 5, c4 = (idx & 31) << 2;
        int gr = row0 + r;
        float px = pts[gr*3 + 0], py = pts[gr*3 + 1], pz = pts[gr*3 + 2];
        float4 v = *(const float4*)&c_sm[r*CLD + c4];
        float o0 = v.x + px*bm_s[c4+0] + py*bm_s[C+c4+0] + pz*bm_s[2*C+c4+0];
        float o1 = v.y + px*bm_s[c4+1] + py*bm_s[C+c4+1] + pz*bm_s[2*C+c4+1];
        float o2 = v.z + px*bm_s[c4+2] + py*bm_s[C+c4+2] + pz*bm_s[2*C+c4+2];
        float o3 = v.w + px*bm_s[c4+3] + py*bm_s[C+c4+3] + pz*bm_s[2*C+c4+3];
        __half2 h0 = __floats2half2_rn(o0, o1);
        __half2 h1 = __floats2half2_rn(o2, o3);
        uint2 o; o.x = *(unsigned*)&h0; o.y = *(unsigned*)&h1;
        *(uint2*)&g_h[(size_t)gr*C + c4] = o;
    }
}

// ---------------------------------------------------------------------------
// K3 (fused): per-CTA pool 128 rows into smem (fp16 gathers), then
// res @ w_out GEMM (f32x2) with fused bias + LayerNorm + relu epilogue.
// ---------------------------------------------------------------------------
#define APAD 132
#define FUSED_SMEM ((128*APAD + 32*128 + 256) * 4)

__global__ __launch_bounds__(256, 2) void k_fused(
    const float* __restrict__ pts,  const float* __restrict__ feat,
    const int*   __restrict__ gidx,
    const float* __restrict__ wout, const float* __restrict__ bout,
    const float* __restrict__ lng,  const float* __restrict__ lnb,
    float* __restrict__ out)
{
    extern __shared__ float sh[];
    float* a_sm = sh;                    // [128][APAD]
    float* ws_  = sh + 128*APAD;         // [32][128]
    float* smu  = ws_ + 32*128;          // [128]
    float* srs  = smu + 128;             // [128]

    const int tid  = threadIdx.x;
    const int wid  = tid >> 5;
    const int lane = tid & 31;
    const int row0 = blockIdx.x * 128;

    // ---- Phase A: pool 128 points into a_sm (warp handles 16 points) ----
    {
        const int c0 = lane << 2;
        const float4 wd = *(const float4*)&g_wd[c0];
        const float4 a0 = *(const float4*)&g_A[c0];
        const float4 a1 = *(const float4*)&g_A[C + c0];
        const float4 a2 = *(const float4*)&g_A[2*C + c0];
        const float4 b2 = *(const float4*)&g_b2[c0];

        for (int t = 0; t < 16; t++) {
            const int pl = wid * 16 + t;
            const int pt = row0 + pl;
            const int base = (pt >> 14) << 14;

            const float cx = pts[pt*3 + 0], cy = pts[pt*3 + 1], cz = pts[pt*3 + 2];
            int j = gidx[pt*KNB + lane] + base;
            const float* gp = &pts[(size_t)j*3];
            float dx = gp[0] - cx, dy = gp[1] - cy, dz = gp[2] - cz;
            float dist = sqrtf(fmaf(dx, dx, fmaf(dy, dy, dz*dz)));

            float4 acc = make_float4(-3.0e38f, -3.0e38f, -3.0e38f, -3.0e38f);
#pragma unroll
            for (int k = 0; k < 32; k++) {
                int   jk = __shfl_sync(0xffffffffu, j,    k);
                float dk = __shfl_sync(0xffffffffu, dist, k);
                uint2 raw = *(const uint2*)&g_h[(size_t)jk*C + c0];
                float2 s01 = __half22float2(*(__half2*)&raw.x);
                float2 s23 = __half22float2(*(__half2*)&raw.y);
                acc.x = fmaxf(acc.x, fmaf(dk, wd.x, s01.x));
                acc.y = fmaxf(acc.y, fmaf(dk, wd.y, s01.y));
                acc.z = fmaxf(acc.z, fmaf(dk, wd.z, s23.x));
                acc.w = fmaxf(acc.w, fmaf(dk, wd.w, s23.y));
            }
            const float4 f = *(const float4*)&feat[(size_t)pt*C + c0];
            float4 r;
            r.x = fmaxf(acc.x + fmaf(cx, a0.x, fmaf(cy, a1.x, fmaf(cz, a2.x, b2.x))), 0.f) + f.x;
            r.y = fmaxf(acc.y + fmaf(cx, a0.y, fmaf(cy, a1.y, fmaf(cz, a2.y, b2.y))), 0.f) + f.y;
            r.z = fmaxf(acc.z + fmaf(cx, a0.z, fmaf(cy, a1.z, fmaf(cz, a2.z, b2.z))), 0.f) + f.z;
            r.w = fmaxf(acc.w + fmaf(cx, a0.w, fmaf(cy, a1.w, fmaf(cz, a2.w, b2.w))), 0.f) + f.w;
            *(float4*)&a_sm[pl*APAD + c0] = r;
        }
    }
    __syncthreads();

    // ---- Phase B: GEMM res @ w_out (f32x2), 8x8 microtile ----
    const int tx = tid & 15, ty = tid >> 4;
    const int r0 = ty * 8, c0g = tx * 8;

    u64 acc2[8][4];
#pragma unroll
    for (int i = 0; i < 8; i++)
#pragma unroll
        for (int j = 0; j < 4; j++) acc2[i][j] = 0ull;

    for (int kc = 0; kc < 128; kc += 32) {
#pragma unroll
        for (int q = tid; q < 1024; q += 256) {
            int kr = q >> 5, cq = (q & 31) << 2;
            float4 v = *(const float4*)&wout[(size_t)(kc + kr)*C + cq];
            *(float4*)&ws_[kr*C + cq] = v;
        }
        __syncthreads();
#pragma unroll 8
        for (int k = 0; k < 32; k++) {
            ulonglong2 wA = *(const ulonglong2*)&ws_[k*C + c0g];
            ulonglong2 wB = *(const ulonglong2*)&ws_[k*C + c0g + 4];
            u64 w2[4] = { wA.x, wA.y, wB.x, wB.y };
#pragma unroll
            for (int i = 0; i < 8; i++) {
                float a = a_sm[(r0 + i)*APAD + kc + k];
                u64 a2 = pack2(a, a);
#pragma unroll
                for (int j = 0; j < 4; j++)
                    acc2[i][j] = fma2(a2, w2[j], acc2[i][j]);
            }
        }
        __syncthreads();
    }

    // ---- Phase C: +bias into a_sm, row stats, LN + relu, store ----
#pragma unroll
    for (int j = 0; j < 4; j++) {
        float2 bj = *(const float2*)&bout[c0g + 2*j];
#pragma unroll
        for (int i = 0; i < 8; i++) {
            float2 v = unpack2(acc2[i][j]);
            a_sm[(r0 + i)*APAD + c0g + 2*j]     = v.x + bj.x;
            a_sm[(r0 + i)*APAD + c0g + 2*j + 1] = v.y + bj.y;
        }
    }
    __syncthreads();

    if (tid < 128) {
        float sum = 0.f, ss = 0.f;
#pragma unroll 8
        for (int c = 0; c < 128; c += 4) {
            float4 x = *(const float4*)&a_sm[tid*APAD + c];
            sum += x.x + x.y + x.z + x.w;
            ss = fmaf(x.x, x.x, fmaf(x.y, x.y, fmaf(x.z, x.z, fmaf(x.w, x.w, ss))));
        }
        float mu  = sum * (1.f/128.f);
        float var = fmaf(ss, 1.f/128.f, -mu*mu);
        smu[tid] = mu;
        srs[tid] = rsqrtf(var + LN_EPS);
    }
    __syncthreads();

#pragma unroll
    for (int it = 0; it < 16; it++) {
        int idx = tid + it * 256;
        int r = idx >> 5, c4 = (idx & 31) << 2;
        float4 x = *(const float4*)&a_sm[r*APAD + c4];
        float4 g = *(const float4*)&lng[c4];
        float4 b = *(const float4*)&lnb[c4];
        float mu = smu[r], rs = srs[r];
        float4 y;
        y.x = fmaxf(fmaf((x.x - mu) * rs, g.x, b.x), 0.f);
        y.y = fmaxf(fmaf((x.y - mu) * rs, g.y, b.y), 0.f);
        y.z = fmaxf(fmaf((x.z - mu) * rs, g.z, b.z), 0.f);
        y.w = fmaxf(fmaf((x.w - mu) * rs, g.w, b.w), 0.f);
        *(float4*)&out[(size_t)(row0 + r)*C + c4] = y;
    }
}

// ---------------------------------------------------------------------------
extern "C" void kernel_launch(void* const* d_in, const int* in_sizes, int n_in,
                              void* d_out, int out_size)
{
    const float* points = (const float*)d_in[0];
    const float* feat   = (const float*)d_in[1];
    const int*   gidx   = (const int*)  d_in[2];
    const float* w_pos  = (const float*)d_in[3];
    const float* b_pos  = (const float*)d_in[4];
    const float* w_gcm  = (const float*)d_in[5];
    const float* b_gcm  = (const float*)d_in[6];
    const float* w_out  = (const float*)d_in[7];
    const float* b_out  = (const float*)d_in[8];
    const float* ln_g   = (const float*)d_in[9];
    const float* ln_b   = (const float*)d_in[10];
    float* out = (float*)d_out;

    cudaFuncSetAttribute(k_gemm_s, cudaFuncAttributeMaxDynamicSharedMemorySize, WMMA_SMEM);
    cudaFuncSetAttribute(k_fused,  cudaFuncAttributeMaxDynamicSharedMemorySize, FUSED_SMEM);

    k_prep   <<<C,        128>>>(w_pos, b_pos, w_gcm, b_gcm);
    k_gemm_s <<<MTOT/128, 256, WMMA_SMEM>>>(feat, points);
    k_fused  <<<MTOT/128, 256, FUSED_SMEM>>>(points, feat, gidx,
                                             w_out, b_out, ln_g, ln_b, out);
}

// round 7
// speedup vs baseline: 2.8739x; 1.3596x over previous
#include <cuda_runtime.h>
#include <cuda_fp16.h>
#include <mma.h>
#include <math.h>
#include <stdint.h>

using namespace nvcuda;

#define BATCH 2
#define NPTS  16384
#define KNB   32
#define C     128
#define MTOT  (BATCH*NPTS)   // 32768
#define LN_EPS 1e-5f

// scratch (device globals; no runtime allocation)
__device__ __half g_h [(size_t)MTOT*C];   // 8 MB, s in fp16
__device__ __half g_bh[(size_t)C*C];      // w_gcm in fp16, [k][n] (row-major B)
__device__ float  g_A [3*C];
__device__ float  g_Bm[3*C];
__device__ float  g_wd[C];
__device__ float  g_b2[C];

// ---------------------------------------------------------------------------
// K1: fold w_pos through w_gcm — 128 CTAs (one per channel), shuffle reduce.
// Also emits g_bh[k][n] = fp16(w_gcm[k][n]) for the wmma GEMM.
// ---------------------------------------------------------------------------
__global__ __launch_bounds__(128) void k_prep(
    const float* __restrict__ w_pos, const float* __restrict__ b_pos,
    const float* __restrict__ w_gcm, const float* __restrict__ b_gcm)
{
    const int c = blockIdx.x;
    const int j = threadIdx.x;
    const int wid  = j >> 5;
    const int lane = j & 31;

    __shared__ float part[11][4];

    const float wc = w_gcm[(size_t)j*C + c];
    g_bh[(size_t)j*C + c] = __float2half_rn(wc);

    float v[11];
#pragma unroll
    for (int i = 0; i < 10; i++) v[i] = w_pos[i*C + j] * wc;
    v[10] = b_pos[j] * wc;

#pragma unroll
    for (int i = 0; i < 11; i++) {
        float x = v[i];
#pragma unroll
        for (int s = 16; s > 0; s >>= 1)
            x += __shfl_xor_sync(0xffffffffu, x, s);
        if (lane == 0) part[i][wid] = x;
    }
    __syncthreads();

    if (j == 0) {
        float pg[11];
#pragma unroll
        for (int i = 0; i < 11; i++)
            pg[i] = part[i][0] + part[i][1] + part[i][2] + part[i][3];
#pragma unroll
        for (int d = 0; d < 3; d++) {
            g_A [d*C + c] = pg[d]     - pg[6 + d];
            g_Bm[d*C + c] = pg[3 + d] + pg[6 + d];
        }
        g_wd[c] = pg[9];
        g_b2[c] = pg[10] + b_gcm[c];
    }
}

// ---------------------------------------------------------------------------
// K2 (wmma tensor core): s = feat @ w_gcm + pts·Bm -> fp16 g_h.
// CTA: 128x128 tile, 256 threads = 8 warps in 4x2; each warp 32x64.
// ---------------------------------------------------------------------------
#define ALD 136                     // a/b smem pitch in halves (272 B)
#define CLD 132                     // c  smem pitch in floats (528 B)
#define WMMA_SMEM (2 * 128 * ALD * 2)        // 69632 B

__global__ __launch_bounds__(256) void k_gemm_s(
    const float* __restrict__ feat, const float* __restrict__ pts)
{
    extern __shared__ char dyn[];
    __half* a_sm = (__half*)dyn;                    // [128][ALD]
    __half* b_sm = (__half*)dyn + 128*ALD;          // [128][ALD]

    const int tid  = threadIdx.x;
    const int wid  = tid >> 5;
    const int row0 = blockIdx.x * 128;

    // stage A: feat fp32 -> fp16 smem
#pragma unroll
    for (int it = 0; it < 16; it++) {
        int idx = tid + it * 256;            // 4096 float4s over 128x128
        int r = idx >> 5, c4 = (idx & 31) << 2;
        float4 v = *(const float4*)&feat[(size_t)(row0 + r)*C + c4];
        __half2 h0 = __floats2half2_rn(v.x, v.y);
        __half2 h1 = __floats2half2_rn(v.z, v.w);
        uint2 o; o.x = *(unsigned*)&h0; o.y = *(unsigned*)&h1;
        *(uint2*)&a_sm[r*ALD + c4] = o;
    }
    // stage B: g_bh fp16 [k][n]
#pragma unroll
    for (int it = 0; it < 8; it++) {
        int idx = tid + it * 256;            // 2048 uint4s over 128x128 halves
        int k = idx >> 4, c8 = (idx & 15) << 3;
        uint4 v = *(const uint4*)&g_bh[(size_t)k*C + c8];
        *(uint4*)&b_sm[k*ALD + c8] = v;
    }
    __syncthreads();

    const int wm = wid >> 1;     // 0..3 -> rows 32*wm
    const int wn = wid & 1;      // 0..1 -> cols 64*wn

    wmma::fragment<wmma::accumulator, 16, 16, 16, float> acc[2][4];
#pragma unroll
    for (int i = 0; i < 2; i++)
#pragma unroll
        for (int j = 0; j < 4; j++) wmma::fill_fragment(acc[i][j], 0.f);

#pragma unroll
    for (int kk = 0; kk < 8; kk++) {
        wmma::fragment<wmma::matrix_a, 16, 16, 16, __half, wmma::row_major> af[2];
        wmma::fragment<wmma::matrix_b, 16, 16, 16, __half, wmma::row_major> bf[4];
#pragma unroll
        for (int i = 0; i < 2; i++)
            wmma::load_matrix_sync(af[i], &a_sm[(wm*32 + i*16)*ALD + kk*16], ALD);
#pragma unroll
        for (int j = 0; j < 4; j++)
            wmma::load_matrix_sync(bf[j], &b_sm[(kk*16)*ALD + wn*64 + j*16], ALD);
#pragma unroll
        for (int i = 0; i < 2; i++)
#pragma unroll
            for (int j = 0; j < 4; j++)
                wmma::mma_sync(acc[i][j], af[i], bf[j], acc[i][j]);
    }
    __syncthreads();

    // epilogue: frags -> fp32 smem, + pts·Bm, fp16 store
    float* c_sm = (float*)dyn;                       // [128][CLD]
    float* bm_s = (float*)dyn + 128*CLD;             // [3*C]
    for (int i = tid; i < 3*C; i += 256) bm_s[i] = g_Bm[i];

#pragma unroll
    for (int i = 0; i < 2; i++)
#pragma unroll
        for (int j = 0; j < 4; j++)
            wmma::store_matrix_sync(&c_sm[(wm*32 + i*16)*CLD + wn*64 + j*16],
                                    acc[i][j], CLD, wmma::mem_row_major);
    __syncthreads();

#pragma unroll
    for (int it = 0; it < 16; it++) {
        int idx = tid + it * 256;
        int r = idx >> 5, c4 = (idx & 31) << 2;
        int gr = row0 + r;
        float px = pts[gr*3 + 0], py = pts[gr*3 + 1], pz = pts[gr*3 + 2];
        float4 v = *(const float4*)&c_sm[r*CLD + c4];
        float o0 = v.x + px*bm_s[c4+0] + py*bm_s[C+c4+0] + pz*bm_s[2*C+c4+0];
        float o1 = v.y + px*bm_s[c4+1] + py*bm_s[C+c4+1] + pz*bm_s[2*C+c4+1];
        float o2 = v.z + px*bm_s[c4+2] + py*bm_s[C+c4+2] + pz*bm_s[2*C+c4+2];
        float o3 = v.w + px*bm_s[c4+3] + py*bm_s[C+c4+3] + pz*bm_s[2*C+c4+3];
        __half2 h0 = __floats2half2_rn(o0, o1);
        __half2 h1 = __floats2half2_rn(o2, o3);
        uint2 o; o.x = *(unsigned*)&h0; o.y = *(unsigned*)&h1;
        *(uint2*)&g_h[(size_t)gr*C + c4] = o;
    }
}

// ---------------------------------------------------------------------------
// K3 (fused): per-CTA pool 128 rows into fp16 smem (wmma A-tile), stage
// w_out fp16 (B-tile), wmma GEMM, fused bias + LayerNorm + relu epilogue.
// smem: a_h[128][ALD] + b_h[128][ALD] halves (stage) aliased by
//       c_sm[128][CLD] + smu[128] + srs[128] floats (epilogue). 69632 B.
// ---------------------------------------------------------------------------
#define FUSED_SMEM (2 * 128 * ALD * 2)   // 69632 B

__global__ __launch_bounds__(256, 2) void k_fused(
    const float* __restrict__ pts,  const float* __restrict__ feat,
    const int*   __restrict__ gidx,
    const float* __restrict__ wout, const float* __restrict__ bout,
    const float* __restrict__ lng,  const float* __restrict__ lnb,
    float* __restrict__ out)
{
    extern __shared__ char dyn[];
    __half* a_h = (__half*)dyn;                     // [128][ALD]
    __half* b_h = (__half*)dyn + 128*ALD;           // [128][ALD]

    const int tid  = threadIdx.x;
    const int wid  = tid >> 5;
    const int lane = tid & 31;
    const int row0 = blockIdx.x * 128;

    // ---- stage B: w_out fp32 -> fp16 smem ----
#pragma unroll
    for (int it = 0; it < 16; it++) {
        int idx = tid + it * 256;            // 4096 float4s over 128x128
        int k = idx >> 5, c4 = (idx & 31) << 2;
        float4 v = *(const float4*)&wout[(size_t)k*C + c4];
        __half2 h0 = __floats2half2_rn(v.x, v.y);
        __half2 h1 = __floats2half2_rn(v.z, v.w);
        uint2 o; o.x = *(unsigned*)&h0; o.y = *(unsigned*)&h1;
        *(uint2*)&b_h[k*ALD + c4] = o;
    }

    // ---- Phase A: pool 128 points into a_h (warp handles 16 points) ----
    {
        const int c0 = lane << 2;
        const float4 wd = *(const float4*)&g_wd[c0];
        const float4 a0 = *(const float4*)&g_A[c0];
        const float4 a1 = *(const float4*)&g_A[C + c0];
        const float4 a2 = *(const float4*)&g_A[2*C + c0];
        const float4 b2 = *(const float4*)&g_b2[c0];

        for (int t = 0; t < 16; t++) {
            const int pl = wid * 16 + t;
            const int pt = row0 + pl;
            const int base = (pt >> 14) << 14;

            const float cx = pts[pt*3 + 0], cy = pts[pt*3 + 1], cz = pts[pt*3 + 2];
            int j = gidx[pt*KNB + lane] + base;
            const float* gp = &pts[(size_t)j*3];
            float dx = gp[0] - cx, dy = gp[1] - cy, dz = gp[2] - cz;
            float dist = sqrtf(fmaf(dx, dx, fmaf(dy, dy, dz*dz)));

            float4 acc = make_float4(-3.0e38f, -3.0e38f, -3.0e38f, -3.0e38f);
#pragma unroll
            for (int k = 0; k < 32; k++) {
                int   jk = __shfl_sync(0xffffffffu, j,    k);
                float dk = __shfl_sync(0xffffffffu, dist, k);
                uint2 raw = *(const uint2*)&g_h[(size_t)jk*C + c0];
                float2 s01 = __half22float2(*(__half2*)&raw.x);
                float2 s23 = __half22float2(*(__half2*)&raw.y);
                acc.x = fmaxf(acc.x, fmaf(dk, wd.x, s01.x));
                acc.y = fmaxf(acc.y, fmaf(dk, wd.y, s01.y));
                acc.z = fmaxf(acc.z, fmaf(dk, wd.z, s23.x));
                acc.w = fmaxf(acc.w, fmaf(dk, wd.w, s23.y));
            }
            const float4 f = *(const float4*)&feat[(size_t)pt*C + c0];
            float4 r;
            r.x = fmaxf(acc.x + fmaf(cx, a0.x, fmaf(cy, a1.x, fmaf(cz, a2.x, b2.x))), 0.f) + f.x;
            r.y = fmaxf(acc.y + fmaf(cx, a0.y, fmaf(cy, a1.y, fmaf(cz, a2.y, b2.y))), 0.f) + f.y;
            r.z = fmaxf(acc.z + fmaf(cx, a0.z, fmaf(cy, a1.z, fmaf(cz, a2.z, b2.z))), 0.f) + f.z;
            r.w = fmaxf(acc.w + fmaf(cx, a0.w, fmaf(cy, a1.w, fmaf(cz, a2.w, b2.w))), 0.f) + f.w;
            __half2 h0 = __floats2half2_rn(r.x, r.y);
            __half2 h1 = __floats2half2_rn(r.z, r.w);
            uint2 o; o.x = *(unsigned*)&h0; o.y = *(unsigned*)&h1;
            *(uint2*)&a_h[pl*ALD + c0] = o;
        }
    }
    __syncthreads();

    // ---- Phase B: wmma GEMM res @ w_out ----
    const int wm = wid >> 1;     // 0..3 -> rows 32*wm
    const int wn = wid & 1;      // 0..1 -> cols 64*wn

    wmma::fragment<wmma::accumulator, 16, 16, 16, float> acc[2][4];
#pragma unroll
    for (int i = 0; i < 2; i++)
#pragma unroll
        for (int j = 0; j < 4; j++) wmma::fill_fragment(acc[i][j], 0.f);

#pragma unroll
    for (int kk = 0; kk < 8; kk++) {
        wmma::fragment<wmma::matrix_a, 16, 16, 16, __half, wmma::row_major> af[2];
        wmma::fragment<wmma::matrix_b, 16, 16, 16, __half, wmma::row_major> bf[4];
#pragma unroll
        for (int i = 0; i < 2; i++)
            wmma::load_matrix_sync(af[i], &a_h[(wm*32 + i*16)*ALD + kk*16], ALD);
#pragma unroll
        for (int j = 0; j < 4; j++)
            wmma::load_matrix_sync(bf[j], &b_h[(kk*16)*ALD + wn*64 + j*16], ALD);
#pragma unroll
        for (int i = 0; i < 2; i++)
#pragma unroll
            for (int j = 0; j < 4; j++)
                wmma::mma_sync(acc[i][j], af[i], bf[j], acc[i][j]);
    }
    __syncthreads();

    // ---- Phase C: frags -> fp32 smem, bias + LN + relu, store ----
    float* c_sm = (float*)dyn;                      // [128][CLD]
    float* smu  = (float*)dyn + 128*CLD;            // [128]
    float* srs  = smu + 128;                        // [128]

#pragma unroll
    for (int i = 0; i < 2; i++)
#pragma unroll
        for (int j = 0; j < 4; j++)
            wmma::store_matrix_sync(&c_sm[(wm*32 + i*16)*CLD + wn*64 + j*16],
                                    acc[i][j], CLD, wmma::mem_row_major);
    __syncthreads();

    if (tid < 128) {
        float sum = 0.f, ss = 0.f;
#pragma unroll 8
        for (int c = 0; c < 128; c += 4) {
            float4 x = *(const float4*)&c_sm[tid*CLD + c];
            float4 b = *(const float4*)&bout[c];
            float v0 = x.x + b.x, v1 = x.y + b.y, v2 = x.z + b.z, v3 = x.w + b.w;
            sum += v0 + v1 + v2 + v3;
            ss = fmaf(v0, v0, fmaf(v1, v1, fmaf(v2, v2, fmaf(v3, v3, ss))));
        }
        float mu  = sum * (1.f/128.f);
        float var = fmaf(ss, 1.f/128.f, -mu*mu);
        smu[tid] = mu;
        srs[tid] = rsqrtf(var + LN_EPS);
    }
    __syncthreads();

#pragma unroll
    for (int it = 0; it < 16; it++) {
        int idx = tid + it * 256;
        int r = idx >> 5, c4 = (idx & 31) << 2;
        float4 x = *(const float4*)&c_sm[r*CLD + c4];
        float4 bb = *(const float4*)&bout[c4];
        float4 g = *(const float4*)&lng[c4];
        float4 lb = *(const float4*)&lnb[c4];
        float mu = smu[r], rs = srs[r];
        float4 y;
        y.x = fmaxf(fmaf((x.x + bb.x - mu) * rs, g.x, lb.x), 0.f);
        y.y = fmaxf(fmaf((x.y + bb.y - mu) * rs, g.y, lb.y), 0.f);
        y.z = fmaxf(fmaf((x.z + bb.z - mu) * rs, g.z, lb.z), 0.f);
        y.w = fmaxf(fmaf((x.w + bb.w - mu) * rs, g.w, lb.w), 0.f);
        *(float4*)&out[(size_t)(row0 + r)*C + c4] = y;
    }
}

// ---------------------------------------------------------------------------
extern "C" void kernel_launch(void* const* d_in, const int* in_sizes, int n_in,
                              void* d_out, int out_size)
{
    const float* points = (const float*)d_in[0];
    const float* feat   = (const float*)d_in[1];
    const int*   gidx   = (const int*)  d_in[2];
    const float* w_pos  = (const float*)d_in[3];
    const float* b_pos  = (const float*)d_in[4];
    const float* w_gcm  = (const float*)d_in[5];
    const float* b_gcm  = (const float*)d_in[6];
    const float* w_out  = (const float*)d_in[7];
    const float* b_out  = (const float*)d_in[8];
    const float* ln_g   = (const float*)d_in[9];
    const float* ln_b   = (const float*)d_in[10];
    float* out = (float*)d_out;

    cudaFuncSetAttribute(k_gemm_s, cudaFuncAttributeMaxDynamicSharedMemorySize, WMMA_SMEM);
    cudaFuncSetAttribute(k_fused,  cudaFuncAttributeMaxDynamicSharedMemorySize, FUSED_SMEM);

    k_prep   <<<C,        128>>>(w_pos, b_pos, w_gcm, b_gcm);
    k_gemm_s <<<MTOT/128, 256, WMMA_SMEM>>>(feat, points);
    k_fused  <<<MTOT/128, 256, FUSED_SMEM>>>(points, feat, gidx,
                                             w_out, b_out, ln_g, ln_b, out);
}

// round 8
// speedup vs baseline: 2.9003x; 1.0092x over previous
#include <cuda_runtime.h>
#include <cuda_fp16.h>
#include <mma.h>
#include <math.h>
#include <stdint.h>

using namespace nvcuda;

#define BATCH 2
#define NPTS  16384
#define KNB   32
#define C     128
#define MTOT  (BATCH*NPTS)   // 32768
#define LN_EPS 1e-5f

// scratch (device globals; no runtime allocation)
__device__ __half g_h [(size_t)MTOT*C];   // 8 MB, s in fp16
__device__ float  g_A [3*C];
__device__ float  g_Bm[3*C];
__device__ float  g_wd[C];
__device__ float  g_b2[C];

// ---------------------------------------------------------------------------
// K1: fold w_pos through w_gcm — 128 CTAs (one per channel), shuffle reduce.
// ---------------------------------------------------------------------------
__global__ __launch_bounds__(128) void k_prep(
    const float* __restrict__ w_pos, const float* __restrict__ b_pos,
    const float* __restrict__ w_gcm, const float* __restrict__ b_gcm)
{
    const int c = blockIdx.x;
    const int j = threadIdx.x;
    const int wid  = j >> 5;
    const int lane = j & 31;

    __shared__ float part[11][4];

    const float wc = w_gcm[(size_t)j*C + c];

    float v[11];
#pragma unroll
    for (int i = 0; i < 10; i++) v[i] = w_pos[i*C + j] * wc;
    v[10] = b_pos[j] * wc;

#pragma unroll
    for (int i = 0; i < 11; i++) {
        float x = v[i];
#pragma unroll
        for (int s = 16; s > 0; s >>= 1)
            x += __shfl_xor_sync(0xffffffffu, x, s);
        if (lane == 0) part[i][wid] = x;
    }
    __syncthreads();

    if (j == 0) {
        float pg[11];
#pragma unroll
        for (int i = 0; i < 11; i++)
            pg[i] = part[i][0] + part[i][1] + part[i][2] + part[i][3];
#pragma unroll
        for (int d = 0; d < 3; d++) {
            g_A [d*C + c] = pg[d]     - pg[6 + d];
            g_Bm[d*C + c] = pg[3 + d] + pg[6 + d];
        }
        g_wd[c] = pg[9];
        g_b2[c] = pg[10] + b_gcm[c];
    }
}

// ---------------------------------------------------------------------------
// K2 (wmma): s = feat @ w_gcm + pts·Bm -> fp16 g_h.
// CTA: 128x128 tile, 256 threads = 8 warps in 4x2; each warp 32x64.
// B staged directly from fp32 w_gcm (no fp16 global round-trip).
// ---------------------------------------------------------------------------
#define ALD 136                     // a/b smem pitch in halves (272 B)
#define CLD 132                     // c  smem pitch in floats (528 B)
#define WMMA_SMEM (2 * 128 * ALD * 2)        // 69632 B

__global__ __launch_bounds__(256, 2) void k_gemm_s(
    const float* __restrict__ feat, const float* __restrict__ wg,
    const float* __restrict__ pts)
{
    extern __shared__ char dyn[];
    __half* a_sm = (__half*)dyn;                    // [128][ALD]
    __half* b_sm = (__half*)dyn + 128*ALD;          // [128][ALD]

    const int tid  = threadIdx.x;
    const int wid  = tid >> 5;
    const int row0 = blockIdx.x * 128;

    // stage A: feat fp32 -> fp16 smem ; stage B: w_gcm fp32 -> fp16 smem
#pragma unroll
    for (int it = 0; it < 16; it++) {
        int idx = tid + it * 256;            // 4096 float4s over 128x128
        int r = idx >> 5, c4 = (idx & 31) << 2;
        float4 v = *(const float4*)&feat[(size_t)(row0 + r)*C + c4];
        __half2 h0 = __floats2half2_rn(v.x, v.y);
        __half2 h1 = __floats2half2_rn(v.z, v.w);
        uint2 o; o.x = *(unsigned*)&h0; o.y = *(unsigned*)&h1;
        *(uint2*)&a_sm[r*ALD + c4] = o;

        float4 w = *(const float4*)&wg[(size_t)r*C + c4];
        __half2 w0 = __floats2half2_rn(w.x, w.y);
        __half2 w1 = __floats2half2_rn(w.z, w.w);
        uint2 ow; ow.x = *(unsigned*)&w0; ow.y = *(unsigned*)&w1;
        *(uint2*)&b_sm[r*ALD + c4] = ow;
    }
    __syncthreads();

    const int wm = wid >> 1;     // 0..3 -> rows 32*wm
    const int wn = wid & 1;      // 0..1 -> cols 64*wn

    wmma::fragment<wmma::accumulator, 16, 16, 16, float> acc[2][4];
#pragma unroll
    for (int i = 0; i < 2; i++)
#pragma unroll
        for (int j = 0; j < 4; j++) wmma::fill_fragment(acc[i][j], 0.f);

#pragma unroll
    for (int kk = 0; kk < 8; kk++) {
        wmma::fragment<wmma::matrix_a, 16, 16, 16, __half, wmma::row_major> af[2];
        wmma::fragment<wmma::matrix_b, 16, 16, 16, __half, wmma::row_major> bf[4];
#pragma unroll
        for (int i = 0; i < 2; i++)
            wmma::load_matrix_sync(af[i], &a_sm[(wm*32 + i*16)*ALD + kk*16], ALD);
#pragma unroll
        for (int j = 0; j < 4; j++)
            wmma::load_matrix_sync(bf[j], &b_sm[(kk*16)*ALD + wn*64 + j*16], ALD);
#pragma unroll
        for (int i = 0; i < 2; i++)
#pragma unroll
            for (int j = 0; j < 4; j++)
                wmma::mma_sync(acc[i][j], af[i], bf[j], acc[i][j]);
    }
    __syncthreads();

    // epilogue: frags -> fp32 smem, + pts·Bm, fp16 store
    float* c_sm = (float*)dyn;                       // [128][CLD]
    float* bm_s = (float*)dyn + 128*CLD;             // [3*C]
    for (int i = tid; i < 3*C; i += 256) bm_s[i] = g_Bm[i];

#pragma unroll
    for (int i = 0; i < 2; i++)
#pragma unroll
        for (int j = 0; j < 4; j++)
            wmma::store_matrix_sync(&c_sm[(wm*32 + i*16)*CLD + wn*64 + j*16],
                                    acc[i][j], CLD, wmma::mem_row_major);
    __syncthreads();

#pragma unroll
    for (int it = 0; it < 16; it++) {
        int idx = tid + it * 256;
        int r = idx >> 5, c4 = (idx & 31) << 2;
        int gr = row0 + r;
        float px = pts[gr*3 + 0], py = pts[gr*3 + 1], pz = pts[gr*3 + 2];
        float4 v = *(const float4*)&c_sm[r*CLD + c4];
        float o0 = v.x + px*bm_s[c4+0] + py*bm_s[C+c4+0] + pz*bm_s[2*C+c4+0];
        float o1 = v.y + px*bm_s[c4+1] + py*bm_s[C+c4+1] + pz*bm_s[2*C+c4+1];
        float o2 = v.z + px*bm_s[c4+2] + py*bm_s[C+c4+2] + pz*bm_s[2*C+c4+2];
        float o3 = v.w + px*bm_s[c4+3] + py*bm_s[C+c4+3] + pz*bm_s[2*C+c4+3];
        __half2 h0 = __floats2half2_rn(o0, o1);
        __half2 h1 = __floats2half2_rn(o2, o3);
        uint2 o; o.x = *(unsigned*)&h0; o.y = *(unsigned*)&h1;
        *(uint2*)&g_h[(size_t)gr*C + c4] = o;
    }
}

// ---------------------------------------------------------------------------
// K3 (fused): pool (2-point interleaved) -> fp16 smem A-tile, wmma GEMM with
// staged fp16 w_out, fused bias + LayerNorm (256-thread stats) + relu.
// smem: stage 2*128*ALD halves = 69632 B; epi floats c_sm+stats = 70656 B.
// ---------------------------------------------------------------------------
#define FUSED_SMEM ((128*CLD + 256 + 512) * 4)    // 70656 B (covers both phases)

__global__ __launch_bounds__(256, 2) void k_fused(
    const float* __restrict__ pts,  const float* __restrict__ feat,
    const int*   __restrict__ gidx,
    const float* __restrict__ wout, const float* __restrict__ bout,
    const float* __restrict__ lng,  const float* __restrict__ lnb,
    float* __restrict__ out)
{
    extern __shared__ char dyn[];
    __half* a_h = (__half*)dyn;                     // [128][ALD]
    __half* b_h = (__half*)dyn + 128*ALD;           // [128][ALD]

    const int tid  = threadIdx.x;
    const int wid  = tid >> 5;
    const int lane = tid & 31;
    const int row0 = blockIdx.x * 128;

    // ---- stage B: w_out fp32 -> fp16 smem ----
#pragma unroll
    for (int it = 0; it < 16; it++) {
        int idx = tid + it * 256;            // 4096 float4s over 128x128
        int k = idx >> 5, c4 = (idx & 31) << 2;
        float4 v = *(const float4*)&wout[(size_t)k*C + c4];
        __half2 h0 = __floats2half2_rn(v.x, v.y);
        __half2 h1 = __floats2half2_rn(v.z, v.w);
        uint2 o; o.x = *(unsigned*)&h0; o.y = *(unsigned*)&h1;
        *(uint2*)&b_h[k*ALD + c4] = o;
    }

    // ---- Phase A: pool 128 points, 2 at a time per warp ----
    {
        const int c0 = lane << 2;
        const float4 wd = *(const float4*)&g_wd[c0];
        const float4 a0 = *(const float4*)&g_A[c0];
        const float4 a1 = *(const float4*)&g_A[C + c0];
        const float4 a2 = *(const float4*)&g_A[2*C + c0];
        const float4 b2 = *(const float4*)&g_b2[c0];

        for (int t = 0; t < 16; t += 2) {
            const int pl0 = wid * 16 + t;
            const int pl1 = pl0 + 1;
            const int pt0 = row0 + pl0;
            const int pt1 = row0 + pl1;
            const int base = (pt0 >> 14) << 14;   // same batch for pt1 (tile ⊂ batch)

            const float cx0 = pts[pt0*3 + 0], cy0 = pts[pt0*3 + 1], cz0 = pts[pt0*3 + 2];
            const float cx1 = pts[pt1*3 + 0], cy1 = pts[pt1*3 + 1], cz1 = pts[pt1*3 + 2];

            int j0 = gidx[pt0*KNB + lane] + base;
            int j1 = gidx[pt1*KNB + lane] + base;
            const float* gp0 = &pts[(size_t)j0*3];
            const float* gp1 = &pts[(size_t)j1*3];
            float dx0 = gp0[0] - cx0, dy0 = gp0[1] - cy0, dz0 = gp0[2] - cz0;
            float dx1 = gp1[0] - cx1, dy1 = gp1[1] - cy1, dz1 = gp1[2] - cz1;
            float dist0 = sqrtf(fmaf(dx0, dx0, fmaf(dy0, dy0, dz0*dz0)));
            float dist1 = sqrtf(fmaf(dx1, dx1, fmaf(dy1, dy1, dz1*dz1)));

            float4 acc0 = make_float4(-3.0e38f, -3.0e38f, -3.0e38f, -3.0e38f);
            float4 acc1 = acc0;
#pragma unroll
            for (int k = 0; k < 32; k++) {
                int   jk0 = __shfl_sync(0xffffffffu, j0,    k);
                int   jk1 = __shfl_sync(0xffffffffu, j1,    k);
                float dk0 = __shfl_sync(0xffffffffu, dist0, k);
                float dk1 = __shfl_sync(0xffffffffu, dist1, k);
                uint2 raw0 = *(const uint2*)&g_h[(size_t)jk0*C + c0];
                uint2 raw1 = *(const uint2*)&g_h[(size_t)jk1*C + c0];
                float2 p01 = __half22float2(*(__half2*)&raw0.x);
                float2 p23 = __half22float2(*(__half2*)&raw0.y);
                float2 q01 = __half22float2(*(__half2*)&raw1.x);
                float2 q23 = __half22float2(*(__half2*)&raw1.y);
                acc0.x = fmaxf(acc0.x, fmaf(dk0, wd.x, p01.x));
                acc0.y = fmaxf(acc0.y, fmaf(dk0, wd.y, p01.y));
                acc0.z = fmaxf(acc0.z, fmaf(dk0, wd.z, p23.x));
                acc0.w = fmaxf(acc0.w, fmaf(dk0, wd.w, p23.y));
                acc1.x = fmaxf(acc1.x, fmaf(dk1, wd.x, q01.x));
                acc1.y = fmaxf(acc1.y, fmaf(dk1, wd.y, q01.y));
                acc1.z = fmaxf(acc1.z, fmaf(dk1, wd.z, q23.x));
                acc1.w = fmaxf(acc1.w, fmaf(dk1, wd.w, q23.y));
            }

            const float4 f0 = *(const float4*)&feat[(size_t)pt0*C + c0];
            const float4 f1 = *(const float4*)&feat[(size_t)pt1*C + c0];
            float4 r0, r1;
            r0.x = fmaxf(acc0.x + fmaf(cx0, a0.x, fmaf(cy0, a1.x, fmaf(cz0, a2.x, b2.x))), 0.f) + f0.x;
            r0.y = fmaxf(acc0.y + fmaf(cx0, a0.y, fmaf(cy0, a1.y, fmaf(cz0, a2.y, b2.y))), 0.f) + f0.y;
            r0.z = fmaxf(acc0.z + fmaf(cx0, a0.z, fmaf(cy0, a1.z, fmaf(cz0, a2.z, b2.z))), 0.f) + f0.z;
            r0.w = fmaxf(acc0.w + fmaf(cx0, a0.w, fmaf(cy0, a1.w, fmaf(cz0, a2.w, b2.w))), 0.f) + f0.w;
            r1.x = fmaxf(acc1.x + fmaf(cx1, a0.x, fmaf(cy1, a1.x, fmaf(cz1, a2.x, b2.x))), 0.f) + f1.x;
            r1.y = fmaxf(acc1.y + fmaf(cx1, a0.y, fmaf(cy1, a1.y, fmaf(cz1, a2.y, b2.y))), 0.f) + f1.y;
            r1.z = fmaxf(acc1.z + fmaf(cx1, a0.z, fmaf(cy1, a1.z, fmaf(cz1, a2.z, b2.z))), 0.f) + f1.z;
            r1.w = fmaxf(acc1.w + fmaf(cx1, a0.w, fmaf(cy1, a1.w, fmaf(cz1, a2.w, b2.w))), 0.f) + f1.w;

            __half2 h0 = __floats2half2_rn(r0.x, r0.y);
            __half2 h1 = __floats2half2_rn(r0.z, r0.w);
            uint2 o0; o0.x = *(unsigned*)&h0; o0.y = *(unsigned*)&h1;
            *(uint2*)&a_h[pl0*ALD + c0] = o0;
            __half2 h2 = __floats2half2_rn(r1.x, r1.y);
            __half2 h3 = __floats2half2_rn(r1.z, r1.w);
            uint2 o1; o1.x = *(unsigned*)&h2; o1.y = *(unsigned*)&h3;
            *(uint2*)&a_h[pl1*ALD + c0] = o1;
        }
    }
    __syncthreads();

    // ---- Phase B: wmma GEMM res @ w_out ----
    const int wm = wid >> 1;
    const int wn = wid & 1;

    wmma::fragment<wmma::accumulator, 16, 16, 16, float> acc[2][4];
#pragma unroll
    for (int i = 0; i < 2; i++)
#pragma unroll
        for (int j = 0; j < 4; j++) wmma::fill_fragment(acc[i][j], 0.f);

#pragma unroll
    for (int kk = 0; kk < 8; kk++) {
        wmma::fragment<wmma::matrix_a, 16, 16, 16, __half, wmma::row_major> af[2];
        wmma::fragment<wmma::matrix_b, 16, 16, 16, __half, wmma::row_major> bf[4];
#pragma unroll
        for (int i = 0; i < 2; i++)
            wmma::load_matrix_sync(af[i], &a_h[(wm*32 + i*16)*ALD + kk*16], ALD);
#pragma unroll
        for (int j = 0; j < 4; j++)
            wmma::load_matrix_sync(bf[j], &b_h[(kk*16)*ALD + wn*64 + j*16], ALD);
#pragma unroll
        for (int i = 0; i < 2; i++)
#pragma unroll
            for (int j = 0; j < 4; j++)
                wmma::mma_sync(acc[i][j], af[i], bf[j], acc[i][j]);
    }
    __syncthreads();

    // ---- Phase C: frags -> fp32 smem, bias + LN (256-thread stats) + relu ----
    float* c_sm = (float*)dyn;                      // [128][CLD]
    float* smu  = (float*)dyn + 128*CLD;            // [128]
    float* srs  = smu + 128;                        // [128]
    float* sp   = srs + 128;                        // [256] partial sums
    float* sq   = sp + 256;                         // [256] partial sumsq

#pragma unroll
    for (int i = 0; i < 2; i++)
#pragma unroll
        for (int j = 0; j < 4; j++)
            wmma::store_matrix_sync(&c_sm[(wm*32 + i*16)*CLD + wn*64 + j*16],
                                    acc[i][j], CLD, wmma::mem_row_major);
    __syncthreads();

    {
        int r = tid & 127, half = tid >> 7;
        int cbeg = half * 64;
        float sum = 0.f, ss = 0.f;
#pragma unroll 8
        for (int c = cbeg; c < cbeg + 64; c += 4) {
            float4 x = *(const float4*)&c_sm[r*CLD + c];
            float4 b = *(const float4*)&bout[c];
            float v0 = x.x + b.x, v1 = x.y + b.y, v2 = x.z + b.z, v3 = x.w + b.w;
            sum += v0 + v1 + v2 + v3;
            ss = fmaf(v0, v0, fmaf(v1, v1, fmaf(v2, v2, fmaf(v3, v3, ss))));
        }
        sp[tid] = sum; sq[tid] = ss;
    }
    __syncthreads();
    if (tid < 128) {
        float sum = sp[tid] + sp[tid + 128];
        float ss  = sq[tid] + sq[tid + 128];
        float mu  = sum * (1.f/128.f);
        float var = fmaf(ss, 1.f/128.f, -mu*mu);
        smu[tid] = mu;
        srs[tid] = rsqrtf(var + LN_EPS);
    }
    __syncthreads();

#pragma unroll
    for (int it = 0; it < 16; it++) {
        int idx = tid + it * 256;
        int r = idx >> 5, c4 = (idx & 31) << 2;
        float4 x = *(const float4*)&c_sm[r*CLD + c4];
        float4 bb = *(const float4*)&bout[c4];
        float4 g = *(const float4*)&lng[c4];
        float4 lb = *(const float4*)&lnb[c4];
        float mu = smu[r], rs = srs[r];
        float4 y;
        y.x = fmaxf(fmaf((x.x + bb.x - mu) * rs, g.x, lb.x), 0.f);
        y.y = fmaxf(fmaf((x.y + bb.y - mu) * rs, g.y, lb.y), 0.f);
        y.z = fmaxf(fmaf((x.z + bb.z - mu) * rs, g.z, lb.z), 0.f);
        y.w = fmaxf(fmaf((x.w + bb.w - mu) * rs, g.w, lb.w), 0.f);
        *(float4*)&out[(size_t)(row0 + r)*C + c4] = y;
    }
}

// ---------------------------------------------------------------------------
extern "C" void kernel_launch(void* const* d_in, const int* in_sizes, int n_in,
                              void* d_out, int out_size)
{
    const float* points = (const float*)d_in[0];
    const float* feat   = (const float*)d_in[1];
    const int*   gidx   = (const int*)  d_in[2];
    const float* w_pos  = (const float*)d_in[3];
    const float* b_pos  = (const float*)d_in[4];
    const float* w_gcm  = (const float*)d_in[5];
    const float* b_gcm  = (const float*)d_in[6];
    const float* w_out  = (const float*)d_in[7];
    const float* b_out  = (const float*)d_in[8];
    const float* ln_g   = (const float*)d_in[9];
    const float* ln_b   = (const float*)d_in[10];
    float* out = (float*)d_out;

    cudaFuncSetAttribute(k_gemm_s, cudaFuncAttributeMaxDynamicSharedMemorySize, WMMA_SMEM);
    cudaFuncSetAttribute(k_fused,  cudaFuncAttributeMaxDynamicSharedMemorySize, FUSED_SMEM);

    k_prep   <<<C,        128>>>(w_pos, b_pos, w_gcm, b_gcm);
    k_gemm_s <<<MTOT/128, 256, WMMA_SMEM>>>(feat, w_gcm, points);
    k_fused  <<<MTOT/128, 256, FUSED_SMEM>>>(points, feat, gidx,
                                             w_out, b_out, ln_g, ln_b, out);
}